// round 10
// baseline (speedup 1.0000x reference)
#include <cuda_runtime.h>
#include <cuda_bf16.h>
#include <cstdint>

#define NN 100000
#define NE 1600000
#define FH 128
#define FO 40

// ======================= device scratch (no allocs allowed) =======================
__device__ int   g_deg[NN];
__device__ float g_dinv[NN];
__device__ float g_rdinv[NN];
__device__ int   g_rowoff[NN + 1];
__device__ int   g_cursor[NN];
__device__ int   g_csr[NE];
__device__ int   g_bsum[128];
__device__ int   g_boff[128];

// int16 row-quantized prescaled activation planes (x*dinv ~= s_row * q)
__device__ unsigned short g_I0[2][(size_t)NN * FH];
__device__ float g_S0[2][NN];
__device__ unsigned short g_I1[(size_t)NN * FH];
__device__ float g_S1[NN];
__device__ unsigned short g_I2[(size_t)NN * FH];
__device__ float g_S2[NN];
// weights (exact hi/lo bf16 split)
__device__ __nv_bfloat16 g_Wth[6 * 128 * 384];   // W^T per layer: [n=128][k=384], hi
__device__ __nv_bfloat16 g_Wtl[6 * 128 * 384];   // lo

// ======================= helpers =======================
__device__ __forceinline__ uint32_t smem_u32(const void* p) {
    uint32_t a;
    asm("{ .reg .u64 t; cvta.to.shared.u64 t, %1; cvt.u32.u64 %0, t; }" : "=r"(a) : "l"(p));
    return a;
}

#define SWZ(off) ((off) ^ (((off) >> 3) & 0x70))

__device__ __forceinline__ void ldmx4(uint32_t* r, uint32_t addr) {
    asm volatile("ldmatrix.sync.aligned.m8n8.x4.shared.b16 {%0,%1,%2,%3}, [%4];"
                 : "=r"(r[0]), "=r"(r[1]), "=r"(r[2]), "=r"(r[3]) : "r"(addr));
}

__device__ __forceinline__ void mma_bf16(float* d, const uint32_t* a, const uint32_t* b) {
    asm volatile(
        "mma.sync.aligned.m16n8k16.row.col.f32.bf16.bf16.f32 "
        "{%0,%1,%2,%3}, {%4,%5,%6,%7}, {%8,%9}, {%0,%1,%2,%3};"
        : "+f"(d[0]), "+f"(d[1]), "+f"(d[2]), "+f"(d[3])
        : "r"(a[0]), "r"(a[1]), "r"(a[2]), "r"(a[3]), "r"(b[0]), "r"(b[1]));
}

__device__ __forceinline__ void cpa16(uint32_t saddr, const void* g, bool pred) {
    asm volatile("cp.async.cg.shared.global [%0], [%1], 16, %2;"
                 :: "r"(saddr), "l"(g), "r"(pred ? 16 : 0) : "memory");
}
#define CP_COMMIT() asm volatile("cp.async.commit_group;" ::: "memory")
#define CP_WAIT(n)  asm volatile("cp.async.wait_group %0;" :: "n"(n) : "memory")

__device__ __forceinline__ uint32_t pack_hi2(float a, float b) {
    __nv_bfloat16 ha = __float2bfloat16(a), hb = __float2bfloat16(b);
    return (uint32_t)__bfloat16_as_ushort(ha) | ((uint32_t)__bfloat16_as_ushort(hb) << 16);
}
__device__ __forceinline__ uint32_t pack_lo2(float a, float b) {
    __nv_bfloat16 ha = __float2bfloat16(a), hb = __float2bfloat16(b);
    __nv_bfloat16 la = __float2bfloat16(a - __bfloat162float(ha));
    __nv_bfloat16 lb = __float2bfloat16(b - __bfloat162float(hb));
    return (uint32_t)__bfloat16_as_ushort(la) | ((uint32_t)__bfloat16_as_ushort(lb) << 16);
}
__device__ __forceinline__ uint32_t packs16(float a, float b, float sinv) {
    int qa = __float2int_rn(a * sinv);
    int qb = __float2int_rn(b * sinv);
    return ((uint32_t)qa & 0xffffu) | ((uint32_t)qb << 16);
}
__device__ __forceinline__ float slo(uint32_t u) { return (float)(short)(u & 0xffffu); }
__device__ __forceinline__ float shi(uint32_t u) { return (float)((int)u >> 16); }

// register dequant: int16 pair (one fragment reg) * scale -> bf16 hi pair + lo pair
// identical math to (pack_hi2, pack_lo2) of the dequanted values.
__device__ __forceinline__ void deq_frag(uint32_t u, float s, uint32_t& hi, uint32_t& lo) {
    float fa = slo(u) * s, fb = shi(u) * s;
    __nv_bfloat16 ha = __float2bfloat16(fa), hb = __float2bfloat16(fb);
    uint32_t hau = (uint32_t)__bfloat16_as_ushort(ha);
    uint32_t hbu = (uint32_t)__bfloat16_as_ushort(hb);
    hi = hau | (hbu << 16);
    float la = fa - __uint_as_float(hau << 16);
    float lb = fb - __uint_as_float(hbu << 16);
    __nv_bfloat16 lA = __float2bfloat16(la), lB = __float2bfloat16(lb);
    lo = (uint32_t)__bfloat16_as_ushort(lA) | ((uint32_t)__bfloat16_as_ushort(lB) << 16);
}

// ======================= graph preprocessing =======================
__global__ void k_hist(const int* __restrict__ dst) {
    int e = blockIdx.x * blockDim.x + threadIdx.x;
    if (e < NE) atomicAdd(&g_deg[dst[e]], 1);
}

__global__ void __launch_bounds__(1024) k_scanA() {
    __shared__ int wsum[32];
    int t = threadIdx.x, lane = t & 31, wp = t >> 5;
    int i = blockIdx.x * 1024 + t;
    int v = (i < NN) ? g_deg[i] : 0;
    int x = v;
    #pragma unroll
    for (int o = 1; o < 32; o <<= 1) {
        int y = __shfl_up_sync(0xffffffffu, x, o);
        if (lane >= o) x += y;
    }
    if (lane == 31) wsum[wp] = x;
    __syncthreads();
    if (wp == 0) {
        int s = wsum[lane];
        #pragma unroll
        for (int o = 1; o < 32; o <<= 1) {
            int y = __shfl_up_sync(0xffffffffu, s, o);
            if (lane >= o) s += y;
        }
        wsum[lane] = s;
    }
    __syncthreads();
    int off = (wp ? wsum[wp - 1] : 0);
    if (i < NN) g_rowoff[i] = off + x - v;
    if (t == 1023) g_bsum[blockIdx.x] = wsum[31];
}

__global__ void k_scanB(int nb) {
    __shared__ int sh[4];
    int t = threadIdx.x, lane = t & 31, wp = t >> 5;
    int v = (t < nb) ? g_bsum[t] : 0;
    int x = v;
    #pragma unroll
    for (int o = 1; o < 32; o <<= 1) {
        int y = __shfl_up_sync(0xffffffffu, x, o);
        if (lane >= o) x += y;
    }
    if (lane == 31) sh[wp] = x;
    __syncthreads();
    int add = 0;
    for (int w = 0; w < wp; ++w) add += sh[w];
    if (t < 128) g_boff[t] = add + x - v;
}

// scanC + dinv fused
__global__ void k_scanC() {
    int i = blockIdx.x * blockDim.x + threadIdx.x;
    if (i < NN) {
        int r = g_rowoff[i] + g_boff[i >> 10];
        g_rowoff[i] = r;
        g_cursor[i] = r;
        int d = g_deg[i];
        float df = (float)(d > 1 ? d : 1);
        g_dinv[i] = rsqrtf(df);
        g_rdinv[i] = sqrtf(df);
    }
    if (i == 0) g_rowoff[NN] = NE;
}

__global__ void k_scatter(const int* __restrict__ src, const int* __restrict__ dst) {
    int e = blockIdx.x * blockDim.x + threadIdx.x;
    if (e < NE) {
        int p = atomicAdd(&g_cursor[dst[e]], 1);
        g_csr[p] = src[e];
    }
}

// ======================= input conversion (warp per row) =======================
__global__ void k_featsplit(const float* __restrict__ f) {
    int w = (blockIdx.x * blockDim.x + threadIdx.x) >> 5;
    int lane = threadIdx.x & 31;
    if (w >= NN) return;
    float dv = g_dinv[w];
    size_t base = (size_t)w * FH + lane * 4;
    float4 v = *(const float4*)(f + base);
    float p0 = v.x * dv, p1 = v.y * dv, p2 = v.z * dv, p3 = v.w * dv;
    float m = fmaxf(fmaxf(fabsf(p0), fabsf(p1)), fmaxf(fabsf(p2), fabsf(p3)));
    #pragma unroll
    for (int o = 16; o >= 1; o >>= 1) m = fmaxf(m, __shfl_xor_sync(0xffffffffu, m, o));
    float sinv = (m > 0.f) ? (32766.f / m) : 0.f;
    uint2 q;
    q.x = packs16(p0, p1, sinv);
    q.y = packs16(p2, p3, sinv);
    *(uint2*)(&g_I0[0][base]) = q;
    if (lane == 0) g_S0[0][w] = m * (1.f / 32766.f);
}

__global__ void k_prep_w(const float* __restrict__ W0, const float* __restrict__ Wh) {
    int i = blockIdx.x * blockDim.x + threadIdx.x;
    if (i >= 6 * 384 * 128) return;
    int l = i / (384 * 128);
    int r = i % (384 * 128);
    int k = r / 128, n = r % 128;
    const float* W = (l == 0) ? W0 : (Wh + (size_t)(l - 1) * 384 * 128);
    float v = W[(size_t)k * 128 + n];
    __nv_bfloat16 h = __float2bfloat16(v);
    float lo = v - __bfloat162float(h);
    size_t o = (size_t)l * 128 * 384 + (size_t)n * 384 + k;
    g_Wth[o] = h;
    g_Wtl[o] = __float2bfloat16(lo);
}

// ======================= SpMM: warp-per-node CSR gather, int16 in/out ============
// (exact R7 version — scalar csr loads, x4 unroll)
// MODE 1: X1p = -dv^2 * sum       MODE 2: X2p = -2*dv^2 * sum - X0p[w]
template <int MODE>
__global__ void __launch_bounds__(256) k_spmm(
    const unsigned short* __restrict__ Yq, const float* __restrict__ Ys,
    const unsigned short* __restrict__ X0q, const float* __restrict__ X0s,
    unsigned short* __restrict__ oq, float* __restrict__ os) {
    int w = (blockIdx.x * blockDim.x + threadIdx.x) >> 5;
    int lane = threadIdx.x & 31;
    if (w >= NN) return;
    int beg = g_rowoff[w];
    int end = g_rowoff[w + 1];
    const size_t lo4 = (size_t)(lane * 4);
    float a0 = 0.f, a1 = 0.f, a2 = 0.f, a3 = 0.f;
    int i = beg;
    for (; i + 4 <= end; i += 4) {
        int s0 = g_csr[i], s1 = g_csr[i + 1], s2 = g_csr[i + 2], s3 = g_csr[i + 3];
        float c0 = Ys[s0], c1 = Ys[s1], c2 = Ys[s2], c3 = Ys[s3];
        uint2 u0 = *(const uint2*)(Yq + (size_t)s0 * FH + lo4);
        uint2 u1 = *(const uint2*)(Yq + (size_t)s1 * FH + lo4);
        uint2 u2 = *(const uint2*)(Yq + (size_t)s2 * FH + lo4);
        uint2 u3 = *(const uint2*)(Yq + (size_t)s3 * FH + lo4);
        a0 = fmaf(slo(u0.x), c0, a0); a1 = fmaf(shi(u0.x), c0, a1);
        a2 = fmaf(slo(u0.y), c0, a2); a3 = fmaf(shi(u0.y), c0, a3);
        a0 = fmaf(slo(u1.x), c1, a0); a1 = fmaf(shi(u1.x), c1, a1);
        a2 = fmaf(slo(u1.y), c1, a2); a3 = fmaf(shi(u1.y), c1, a3);
        a0 = fmaf(slo(u2.x), c2, a0); a1 = fmaf(shi(u2.x), c2, a1);
        a2 = fmaf(slo(u2.y), c2, a2); a3 = fmaf(shi(u2.y), c2, a3);
        a0 = fmaf(slo(u3.x), c3, a0); a1 = fmaf(shi(u3.x), c3, a1);
        a2 = fmaf(slo(u3.y), c3, a2); a3 = fmaf(shi(u3.y), c3, a3);
    }
    for (; i < end; ++i) {
        int s0 = g_csr[i];
        float c0 = Ys[s0];
        uint2 u0 = *(const uint2*)(Yq + (size_t)s0 * FH + lo4);
        a0 = fmaf(slo(u0.x), c0, a0); a1 = fmaf(shi(u0.x), c0, a1);
        a2 = fmaf(slo(u0.y), c0, a2); a3 = fmaf(shi(u0.y), c0, a3);
    }
    float dv = g_dinv[w];
    float dv2 = dv * dv;
    float p0, p1, p2, p3;
    if (MODE == 1) {
        float m = -dv2;
        p0 = m * a0; p1 = m * a1; p2 = m * a2; p3 = m * a3;
    } else {
        float xs = X0s[w];
        uint2 xq = *(const uint2*)(X0q + (size_t)w * FH + lo4);
        float m = -2.f * dv2;
        p0 = fmaf(m, a0, -slo(xq.x) * xs);
        p1 = fmaf(m, a1, -shi(xq.x) * xs);
        p2 = fmaf(m, a2, -slo(xq.y) * xs);
        p3 = fmaf(m, a3, -shi(xq.y) * xs);
    }
    float mx = fmaxf(fmaxf(fabsf(p0), fabsf(p1)), fmaxf(fabsf(p2), fabsf(p3)));
    #pragma unroll
    for (int o = 16; o >= 1; o >>= 1) mx = fmaxf(mx, __shfl_xor_sync(0xffffffffu, mx, o));
    float sinv = (mx > 0.f) ? (32766.f / mx) : 0.f;
    uint2 q;
    q.x = packs16(p0, p1, sinv);
    q.y = packs16(p2, p3, sinv);
    *(uint2*)(oq + (size_t)w * FH + lo4) = q;
    if (lane == 0) os[w] = mx * (1.f / 32766.f);
}

// ======================= pipelined mma.sync GEMM, register dequant ===============
// C = relu( rdinv[m] * ([X0p|X1p|X2p] @ W) + b ); p = C*dinv[m]; store int16+scale.
// A int16 chunk lands SWIZZLED in scratch; ldmatrix reads int16 fragments directly;
// dequant to bf16 hi/lo happens in registers (no smem round-trip).
// Per stage: scratch(int16 A, swizzled) 16K | B_hi 16K | B_lo 16K  = 48K; x2 stages.
#define GS_SCR 0
#define GS_BHI 16384
#define GS_BLO 32768
#define GS_ST  49152
#define GM_SMEM_SZ (2 * GS_ST)

__global__ void __launch_bounds__(512) k_gemm_mma(
    const unsigned short* __restrict__ x0q, const float* __restrict__ x0s,
    const float* __restrict__ bias,
    const __nv_bfloat16* __restrict__ wth, const __nv_bfloat16* __restrict__ wtl,
    unsigned short* __restrict__ outq, float* __restrict__ outs) {
    extern __shared__ char smem_raw[];
    __shared__ float s_bias[128];
    __shared__ float s_scl[3][128];
    __shared__ float s_rmax[128][4];
    uint32_t sb0 = smem_u32(smem_raw);
    uint32_t sb = (sb0 + 1023u) & ~1023u;          // 1024B-align for SW128

    const int tid = threadIdx.x, lane = tid & 31, wid = tid >> 5;
    const int wm = wid >> 2, wn = wid & 3;         // 4x4 warp grid
    const int rowBase = blockIdx.x * 128;

    const unsigned short* Aq[3] = {x0q, g_I1, g_I2};
    const float* Sq[3] = {x0s, g_S1, g_S2};
    if (tid < 128) {
        s_bias[tid] = bias[tid];
        int row = rowBase + tid;
        bool ok = row < NN;
        #pragma unroll
        for (int b = 0; b < 3; ++b)
            s_scl[b][tid] = ok ? Sq[b][row] : 0.f;
    }
    __syncthreads();

    float acc[2][4][4];
    #pragma unroll
    for (int a = 0; a < 2; ++a)
        #pragma unroll
        for (int b = 0; b < 4; ++b)
            #pragma unroll
            for (int c = 0; c < 4; ++c) acc[a][b][c] = 0.f;

    const int lrow = lane & 7, seg = lane >> 3;

    auto load_chunk = [&](uint32_t st, int kc) {
        const int coff = (kc & 1) * 64;
        const unsigned short* __restrict__ aq = Aq[kc >> 1];
        #pragma unroll
        for (int t = 0; t < 2; ++t) {
            int idx = tid + t * 512;
            int r = idx >> 3, j = idx & 7;
            int row = rowBase + r;
            bool ok = row < NN;
            int rowc = ok ? row : (NN - 1);
            uint32_t sw = SWZ((uint32_t)(r * 128 + j * 16));
            cpa16(st + GS_SCR + sw, aq + (size_t)rowc * FH + coff + j * 8, ok);
        }
        #pragma unroll
        for (int t = 0; t < 2; ++t) {
            int idx = tid + t * 512;
            int n = idx >> 3, j = idx & 7;
            uint32_t sw = SWZ((uint32_t)(n * 128 + j * 16));
            cpa16(st + GS_BHI + sw, wth + (size_t)n * 384 + kc * 64 + j * 8, true);
            cpa16(st + GS_BLO + sw, wtl + (size_t)n * 384 + kc * 64 + j * 8, true);
        }
    };

    load_chunk(sb, 0);
    CP_COMMIT();

    #pragma unroll 1
    for (int kc = 0; kc < 6; ++kc) {
        if (kc < 5) {
            load_chunk(sb + (((kc + 1) & 1) ? GS_ST : 0), kc + 1);
            CP_COMMIT();
            CP_WAIT(1);
        } else {
            CP_WAIT(0);
        }
        __syncthreads();

        const uint32_t st = sb + ((kc & 1) ? GS_ST : 0);
        // fragment-row scales for this basis (rows fixed across kt)
        const float* sc = s_scl[kc >> 1];
        float sA0[2], sA1[2];
        #pragma unroll
        for (int mt = 0; mt < 2; ++mt) {
            int rb = wm * 32 + mt * 16 + (lane >> 2);
            sA0[mt] = sc[rb];
            sA1[mt] = sc[rb + 8];
        }

        #pragma unroll
        for (int kt = 0; kt < 4; ++kt) {
            uint32_t Ahf[2][4], Alf[2][4], Bhf[2][4], Blf[2][4];
            #pragma unroll
            for (int mt = 0; mt < 2; ++mt) {
                int m = wm * 32 + mt * 16 + (seg & 1) * 8 + lrow;
                int kb = kt * 32 + (seg >> 1) * 16;
                uint32_t sw = SWZ((uint32_t)(m * 128 + kb));
                uint32_t q4[4];
                ldmx4(q4, st + GS_SCR + sw);
                // regs {0,2} belong to row (lane>>2), {1,3} to row+8
                deq_frag(q4[0], sA0[mt], Ahf[mt][0], Alf[mt][0]);
                deq_frag(q4[1], sA1[mt], Ahf[mt][1], Alf[mt][1]);
                deq_frag(q4[2], sA0[mt], Ahf[mt][2], Alf[mt][2]);
                deq_frag(q4[3], sA1[mt], Ahf[mt][3], Alf[mt][3]);
            }
            #pragma unroll
            for (int ntp = 0; ntp < 2; ++ntp) {
                int n = wn * 32 + ntp * 16 + (seg >> 1) * 8 + lrow;
                int kb = kt * 32 + (seg & 1) * 16;
                uint32_t sw = SWZ((uint32_t)(n * 128 + kb));
                ldmx4(Bhf[ntp], st + GS_BHI + sw);
                ldmx4(Blf[ntp], st + GS_BLO + sw);
            }
            #pragma unroll
            for (int mt = 0; mt < 2; ++mt)
                #pragma unroll
                for (int ntp = 0; ntp < 2; ++ntp)
                    #pragma unroll
                    for (int sub = 0; sub < 2; ++sub) {
                        int nj = ntp * 2 + sub;
                        mma_bf16(acc[mt][nj], Ahf[mt], &Bhf[ntp][sub * 2]);
                        mma_bf16(acc[mt][nj], Ahf[mt], &Blf[ntp][sub * 2]);
                        mma_bf16(acc[mt][nj], Alf[mt], &Bhf[ntp][sub * 2]);
                    }
        }
        __syncthreads();
    }

    // ---- epilogue: p = relu(acc*rdinv + b)*dinv; rowmax-quantize to int16 ----
    float dvr[2][2], rdr[2][2];
    #pragma unroll
    for (int mt = 0; mt < 2; ++mt)
        #pragma unroll
        for (int rp = 0; rp < 2; ++rp) {
            int row = rowBase + wm * 32 + mt * 16 + (lane >> 2) + rp * 8;
            bool ok = row < NN;
            dvr[mt][rp] = ok ? g_dinv[row] : 0.f;
            rdr[mt][rp] = ok ? g_rdinv[row] : 0.f;
        }
    float pm[2][2] = {{0.f, 0.f}, {0.f, 0.f}};
    #pragma unroll
    for (int mt = 0; mt < 2; ++mt)
        #pragma unroll
        for (int nj = 0; nj < 4; ++nj) {
            int col = wn * 32 + nj * 8 + (lane & 3) * 2;
            float bz0 = s_bias[col], bz1 = s_bias[col + 1];
            #pragma unroll
            for (int rp = 0; rp < 2; ++rp) {
                float rd = rdr[mt][rp], dv = dvr[mt][rp];
                float p0 = fmaxf(fmaf(acc[mt][nj][rp * 2 + 0], rd, bz0), 0.f) * dv;
                float p1 = fmaxf(fmaf(acc[mt][nj][rp * 2 + 1], rd, bz1), 0.f) * dv;
                pm[mt][rp] = fmaxf(pm[mt][rp], fmaxf(p0, p1));
            }
        }
    #pragma unroll
    for (int mt = 0; mt < 2; ++mt)
        #pragma unroll
        for (int rp = 0; rp < 2; ++rp) {
            float m = pm[mt][rp];
            m = fmaxf(m, __shfl_xor_sync(0xffffffffu, m, 1));
            m = fmaxf(m, __shfl_xor_sync(0xffffffffu, m, 2));
            if ((lane & 3) == 0)
                s_rmax[wm * 32 + mt * 16 + rp * 8 + (lane >> 2)][wn] = m;
        }
    __syncthreads();
    #pragma unroll
    for (int mt = 0; mt < 2; ++mt)
        #pragma unroll
        for (int rp = 0; rp < 2; ++rp) {
            int rl = wm * 32 + mt * 16 + rp * 8 + (lane >> 2);
            int row = rowBase + rl;
            float rm = fmaxf(fmaxf(s_rmax[rl][0], s_rmax[rl][1]),
                             fmaxf(s_rmax[rl][2], s_rmax[rl][3]));
            float sinv = (rm > 0.f) ? (32766.f / rm) : 0.f;
            if (wn == 0 && (lane & 3) == 0 && row < NN)
                outs[row] = rm * (1.f / 32766.f);
            if (row < NN) {
                float rd = rdr[mt][rp], dv = dvr[mt][rp];
                #pragma unroll
                for (int nj = 0; nj < 4; ++nj) {
                    int col = wn * 32 + nj * 8 + (lane & 3) * 2;
                    float bz0 = s_bias[col], bz1 = s_bias[col + 1];
                    float p0 = fmaxf(fmaf(acc[mt][nj][rp * 2 + 0], rd, bz0), 0.f) * dv;
                    float p1 = fmaxf(fmaf(acc[mt][nj][rp * 2 + 1], rd, bz1), 0.f) * dv;
                    *(uint32_t*)(outq + (size_t)row * FH + col) = packs16(p0, p1, sinv);
                }
            }
        }
}

// ======================= SIMT GEMM for final layer (CO=40) =======================
template <int CO, int TM, int TN>
__global__ void k_gemm_simt(
    const unsigned short* __restrict__ X0q, const float* __restrict__ X0s,
    const unsigned short* __restrict__ X1q, const float* __restrict__ X1s,
    const unsigned short* __restrict__ X2q, const float* __restrict__ X2s,
    const float* __restrict__ W, const float* __restrict__ bias,
    float* __restrict__ out) {
    constexpr int BM = 128, BK = 16;
    constexpr int NTX = CO / TN;
    constexpr int NTY = BM / TM;
    constexpr int NT = NTX * NTY;
    __shared__ float As[BK][BM + 1];
    __shared__ float Bs[BK][CO];
    const int tid = threadIdx.x;
    const int tx = tid % NTX;
    const int ty = tid / NTX;
    const int rowBase = blockIdx.x * BM;

    float acc[TM][TN];
    #pragma unroll
    for (int m = 0; m < TM; ++m)
        #pragma unroll
        for (int n = 0; n < TN; ++n) acc[m][n] = 0.f;

    #pragma unroll 1
    for (int kt = 0; kt < 24; ++kt) {
        const unsigned short* __restrict__ Xq = (kt < 8) ? X0q : ((kt < 16) ? X1q : X2q);
        const float* __restrict__ Xs = (kt < 8) ? X0s : ((kt < 16) ? X1s : X2s);
        const int kcol = (kt & 7) * BK;
        for (int i = tid; i < BM * BK; i += NT) {
            int r = i >> 4, k = i & 15;
            int row = rowBase + r;
            float v = 0.f;
            if (row < NN) {
                size_t off = (size_t)row * FH + kcol + k;
                v = (float)(short)Xq[off] * Xs[row] * g_rdinv[row];
            }
            As[k][r] = v;
        }
        for (int i = tid; i < BK * CO; i += NT) {
            int k = i / CO, c = i % CO;
            Bs[k][c] = W[(size_t)(kt * BK + k) * CO + c];
        }
        __syncthreads();
        #pragma unroll
        for (int k = 0; k < BK; ++k) {
            float ra[TM], rb[TN];
            #pragma unroll
            for (int m = 0; m < TM; ++m) ra[m] = As[k][ty * TM + m];
            #pragma unroll
            for (int n = 0; n < TN; ++n) rb[n] = Bs[k][tx * TN + n];
            #pragma unroll
            for (int m = 0; m < TM; ++m)
                #pragma unroll
                for (int n = 0; n < TN; ++n)
                    acc[m][n] = fmaf(ra[m], rb[n], acc[m][n]);
        }
        __syncthreads();
    }
    #pragma unroll
    for (int m = 0; m < TM; ++m) {
        int row = rowBase + ty * TM + m;
        if (row < NN) {
            #pragma unroll
            for (int n = 0; n < TN; ++n) {
                int c = tx * TN + n;
                out[(size_t)row * CO + c] = fmaxf(acc[m][n] + bias[c], 0.f);
            }
        }
    }
}

// ======================= host launcher =======================
extern "C" void kernel_launch(void* const* d_in, const int* in_sizes, int n_in,
                              void* d_out, int out_size) {
    const float* feat = (const float*)d_in[0];
    const int*   src  = (const int*)d_in[1];
    const int*   dst  = (const int*)d_in[2];
    const float* W0   = (const float*)d_in[3];
    const float* b0   = (const float*)d_in[4];
    const float* Wh   = (const float*)d_in[5];
    const float* bh   = (const float*)d_in[6];
    const float* Wl   = (const float*)d_in[7];
    const float* bl   = (const float*)d_in[8];
    float* out = (float*)d_out;

    unsigned short *I0, *I1, *I2;
    float *S0, *S1, *S2;
    __nv_bfloat16 *Wth, *Wtl;
    int* degp;
    cudaGetSymbolAddress((void**)&I0,  g_I0);
    cudaGetSymbolAddress((void**)&I1,  g_I1);
    cudaGetSymbolAddress((void**)&I2,  g_I2);
    cudaGetSymbolAddress((void**)&S0,  g_S0);
    cudaGetSymbolAddress((void**)&S1,  g_S1);
    cudaGetSymbolAddress((void**)&S2,  g_S2);
    cudaGetSymbolAddress((void**)&Wth, g_Wth);
    cudaGetSymbolAddress((void**)&Wtl, g_Wtl);
    cudaGetSymbolAddress((void**)&degp, g_deg);

    cudaFuncSetAttribute(k_gemm_mma, cudaFuncAttributeMaxDynamicSharedMemorySize,
                         GM_SMEM_SZ + 1024);

    const int TPB = 256;
    const int nodeBlocks = (NN + TPB - 1) / TPB;
    const int edgeBlocks = (NE + TPB - 1) / TPB;
    const int scanBlocks = (NN + 1023) / 1024;   // 98

    // preprocessing
    cudaMemsetAsync(degp, 0, NN * sizeof(int));
    k_hist<<<edgeBlocks, TPB>>>(dst);
    k_scanA<<<scanBlocks, 1024>>>();
    k_scanB<<<1, 128>>>(scanBlocks);
    k_scanC<<<nodeBlocks, TPB>>>();   // + dinv/rdinv
    k_scatter<<<edgeBlocks, TPB>>>(src, dst);

    // input conversion (warp per row)
    k_featsplit<<<(NN * 32 + TPB - 1) / TPB, TPB>>>(feat);
    k_prep_w<<<(6 * 384 * 128 + TPB - 1) / TPB, TPB>>>(W0, Wh);

    const size_t SL = (size_t)NN * FH;
    const int spmmBlocks = (NN * 32 + TPB - 1) / TPB;
    const int tileBlocks = (NN + 127) / 128;

    int cur = 0;
    for (int l = 0; l < 7; ++l) {
        const unsigned short* I0c = I0 + (size_t)cur * SL;
        const float* S0c = S0 + (size_t)cur * NN;
        k_spmm<1><<<spmmBlocks, TPB>>>(I0c, S0c, nullptr, nullptr, I1, S1);
        k_spmm<2><<<spmmBlocks, TPB>>>(I1, S1, I0c, S0c, I2, S2);
        if (l < 6) {
            const float* bias = (l == 0) ? b0 : (bh + (size_t)(l - 1) * 128);
            int nxt = 1 - cur;
            k_gemm_mma<<<tileBlocks, 512, GM_SMEM_SZ + 1024>>>(
                I0c, S0c, bias,
                Wth + (size_t)l * 128 * 384, Wtl + (size_t)l * 128 * 384,
                I0 + (size_t)nxt * SL, S0 + (size_t)nxt * NN);
            cur = nxt;
        } else {
            k_gemm_simt<FO, 8, 5><<<tileBlocks, 128>>>(
                I0c, S0c, I1, S1, I2, S2, Wl, bl, out);
        }
    }
}

// round 11
// speedup vs baseline: 1.1298x; 1.1298x over previous
#include <cuda_runtime.h>
#include <cuda_bf16.h>
#include <cstdint>

#define NN 100000
#define NE 1600000
#define FH 128
#define FO 40

// ======================= device scratch (no allocs allowed) =======================
__device__ int   g_deg[NN];
__device__ float g_dinv[NN];
__device__ float g_rdinv[NN];
__device__ int   g_rowoff[NN + 1];
__device__ int   g_cursor[NN];
__device__ int   g_csr[NE];
__device__ int   g_bsum[128];
__device__ int   g_boff[128];

// int16 row-quantized prescaled activation planes (x*dinv ~= s_row * q)
__device__ unsigned short g_I0[2][(size_t)NN * FH];
__device__ float g_S0[2][NN];
__device__ unsigned short g_I1[(size_t)NN * FH];
__device__ float g_S1[NN];
__device__ unsigned short g_I2[(size_t)NN * FH];
__device__ float g_S2[NN];
// weights (exact hi/lo bf16 split)
__device__ __nv_bfloat16 g_Wth[6 * 128 * 384];   // W^T per layer: [n=128][k=384], hi
__device__ __nv_bfloat16 g_Wtl[6 * 128 * 384];   // lo

// ======================= helpers =======================
__device__ __forceinline__ uint32_t smem_u32(const void* p) {
    uint32_t a;
    asm("{ .reg .u64 t; cvta.to.shared.u64 t, %1; cvt.u32.u64 %0, t; }" : "=r"(a) : "l"(p));
    return a;
}

#define SWZ(off) ((off) ^ (((off) >> 3) & 0x70))

__device__ __forceinline__ void ldmx4(uint32_t* r, uint32_t addr) {
    asm volatile("ldmatrix.sync.aligned.m8n8.x4.shared.b16 {%0,%1,%2,%3}, [%4];"
                 : "=r"(r[0]), "=r"(r[1]), "=r"(r[2]), "=r"(r[3]) : "r"(addr));
}

__device__ __forceinline__ void mma_bf16(float* d, const uint32_t* a, const uint32_t* b) {
    asm volatile(
        "mma.sync.aligned.m16n8k16.row.col.f32.bf16.bf16.f32 "
        "{%0,%1,%2,%3}, {%4,%5,%6,%7}, {%8,%9}, {%0,%1,%2,%3};"
        : "+f"(d[0]), "+f"(d[1]), "+f"(d[2]), "+f"(d[3])
        : "r"(a[0]), "r"(a[1]), "r"(a[2]), "r"(a[3]), "r"(b[0]), "r"(b[1]));
}

__device__ __forceinline__ void cpa16(uint32_t saddr, const void* g, bool pred) {
    asm volatile("cp.async.cg.shared.global [%0], [%1], 16, %2;"
                 :: "r"(saddr), "l"(g), "r"(pred ? 16 : 0) : "memory");
}
#define CP_COMMIT() asm volatile("cp.async.commit_group;" ::: "memory")
#define CP_WAIT(n)  asm volatile("cp.async.wait_group %0;" :: "n"(n) : "memory")

__device__ __forceinline__ uint32_t pack_hi2(float a, float b) {
    __nv_bfloat16 ha = __float2bfloat16(a), hb = __float2bfloat16(b);
    return (uint32_t)__bfloat16_as_ushort(ha) | ((uint32_t)__bfloat16_as_ushort(hb) << 16);
}
__device__ __forceinline__ uint32_t pack_lo2(float a, float b) {
    __nv_bfloat16 ha = __float2bfloat16(a), hb = __float2bfloat16(b);
    __nv_bfloat16 la = __float2bfloat16(a - __bfloat162float(ha));
    __nv_bfloat16 lb = __float2bfloat16(b - __bfloat162float(hb));
    return (uint32_t)__bfloat16_as_ushort(la) | ((uint32_t)__bfloat16_as_ushort(lb) << 16);
}
__device__ __forceinline__ uint32_t packs16(float a, float b, float sinv) {
    int qa = __float2int_rn(a * sinv);
    int qb = __float2int_rn(b * sinv);
    return ((uint32_t)qa & 0xffffu) | ((uint32_t)qb << 16);
}
__device__ __forceinline__ float slo(uint32_t u) { return (float)(short)(u & 0xffffu); }
__device__ __forceinline__ float shi(uint32_t u) { return (float)((int)u >> 16); }

// ======================= graph preprocessing =======================
__global__ void k_hist(const int* __restrict__ dst) {
    int e = blockIdx.x * blockDim.x + threadIdx.x;
    if (e < NE) atomicAdd(&g_deg[dst[e]], 1);
}

__global__ void __launch_bounds__(1024) k_scanA() {
    __shared__ int wsum[32];
    int t = threadIdx.x, lane = t & 31, wp = t >> 5;
    int i = blockIdx.x * 1024 + t;
    int v = (i < NN) ? g_deg[i] : 0;
    int x = v;
    #pragma unroll
    for (int o = 1; o < 32; o <<= 1) {
        int y = __shfl_up_sync(0xffffffffu, x, o);
        if (lane >= o) x += y;
    }
    if (lane == 31) wsum[wp] = x;
    __syncthreads();
    if (wp == 0) {
        int s = wsum[lane];
        #pragma unroll
        for (int o = 1; o < 32; o <<= 1) {
            int y = __shfl_up_sync(0xffffffffu, s, o);
            if (lane >= o) s += y;
        }
        wsum[lane] = s;
    }
    __syncthreads();
    int off = (wp ? wsum[wp - 1] : 0);
    if (i < NN) g_rowoff[i] = off + x - v;
    if (t == 1023) g_bsum[blockIdx.x] = wsum[31];
}

__global__ void k_scanB(int nb) {
    __shared__ int sh[4];
    int t = threadIdx.x, lane = t & 31, wp = t >> 5;
    int v = (t < nb) ? g_bsum[t] : 0;
    int x = v;
    #pragma unroll
    for (int o = 1; o < 32; o <<= 1) {
        int y = __shfl_up_sync(0xffffffffu, x, o);
        if (lane >= o) x += y;
    }
    if (lane == 31) sh[wp] = x;
    __syncthreads();
    int add = 0;
    for (int w = 0; w < wp; ++w) add += sh[w];
    if (t < 128) g_boff[t] = add + x - v;
}

// scanC + dinv fused
__global__ void k_scanC() {
    int i = blockIdx.x * blockDim.x + threadIdx.x;
    if (i < NN) {
        int r = g_rowoff[i] + g_boff[i >> 10];
        g_rowoff[i] = r;
        g_cursor[i] = r;
        int d = g_deg[i];
        float df = (float)(d > 1 ? d : 1);
        g_dinv[i] = rsqrtf(df);
        g_rdinv[i] = sqrtf(df);
    }
    if (i == 0) g_rowoff[NN] = NE;
}

__global__ void k_scatter(const int* __restrict__ src, const int* __restrict__ dst) {
    int e = blockIdx.x * blockDim.x + threadIdx.x;
    if (e < NE) {
        int p = atomicAdd(&g_cursor[dst[e]], 1);
        g_csr[p] = src[e];
    }
}

// ======================= input conversion (warp per row) =======================
__global__ void k_featsplit(const float* __restrict__ f) {
    int w = (blockIdx.x * blockDim.x + threadIdx.x) >> 5;
    int lane = threadIdx.x & 31;
    if (w >= NN) return;
    float dv = g_dinv[w];
    size_t base = (size_t)w * FH + lane * 4;
    float4 v = *(const float4*)(f + base);
    float p0 = v.x * dv, p1 = v.y * dv, p2 = v.z * dv, p3 = v.w * dv;
    float m = fmaxf(fmaxf(fabsf(p0), fabsf(p1)), fmaxf(fabsf(p2), fabsf(p3)));
    #pragma unroll
    for (int o = 16; o >= 1; o >>= 1) m = fmaxf(m, __shfl_xor_sync(0xffffffffu, m, o));
    float sinv = (m > 0.f) ? (32766.f / m) : 0.f;
    uint2 q;
    q.x = packs16(p0, p1, sinv);
    q.y = packs16(p2, p3, sinv);
    *(uint2*)(&g_I0[0][base]) = q;
    if (lane == 0) g_S0[0][w] = m * (1.f / 32766.f);
}

__global__ void k_prep_w(const float* __restrict__ W0, const float* __restrict__ Wh) {
    int i = blockIdx.x * blockDim.x + threadIdx.x;
    if (i >= 6 * 384 * 128) return;
    int l = i / (384 * 128);
    int r = i % (384 * 128);
    int k = r / 128, n = r % 128;
    const float* W = (l == 0) ? W0 : (Wh + (size_t)(l - 1) * 384 * 128);
    float v = W[(size_t)k * 128 + n];
    __nv_bfloat16 h = __float2bfloat16(v);
    float lo = v - __bfloat162float(h);
    size_t o = (size_t)l * 128 * 384 + (size_t)n * 384 + k;
    g_Wth[o] = h;
    g_Wtl[o] = __float2bfloat16(lo);
}

// ======================= SpMM: warp-per-node CSR gather, int16 in/out ============
// (exact R7 champion version — scalar csr loads, x4 unroll)
// MODE 1: X1p = -dv^2 * sum       MODE 2: X2p = -2*dv^2 * sum - X0p[w]
template <int MODE>
__global__ void __launch_bounds__(256) k_spmm(
    const unsigned short* __restrict__ Yq, const float* __restrict__ Ys,
    const unsigned short* __restrict__ X0q, const float* __restrict__ X0s,
    unsigned short* __restrict__ oq, float* __restrict__ os) {
    int w = (blockIdx.x * blockDim.x + threadIdx.x) >> 5;
    int lane = threadIdx.x & 31;
    if (w >= NN) return;
    int beg = g_rowoff[w];
    int end = g_rowoff[w + 1];
    const size_t lo4 = (size_t)(lane * 4);
    float a0 = 0.f, a1 = 0.f, a2 = 0.f, a3 = 0.f;
    int i = beg;
    for (; i + 4 <= end; i += 4) {
        int s0 = g_csr[i], s1 = g_csr[i + 1], s2 = g_csr[i + 2], s3 = g_csr[i + 3];
        float c0 = Ys[s0], c1 = Ys[s1], c2 = Ys[s2], c3 = Ys[s3];
        uint2 u0 = *(const uint2*)(Yq + (size_t)s0 * FH + lo4);
        uint2 u1 = *(const uint2*)(Yq + (size_t)s1 * FH + lo4);
        uint2 u2 = *(const uint2*)(Yq + (size_t)s2 * FH + lo4);
        uint2 u3 = *(const uint2*)(Yq + (size_t)s3 * FH + lo4);
        a0 = fmaf(slo(u0.x), c0, a0); a1 = fmaf(shi(u0.x), c0, a1);
        a2 = fmaf(slo(u0.y), c0, a2); a3 = fmaf(shi(u0.y), c0, a3);
        a0 = fmaf(slo(u1.x), c1, a0); a1 = fmaf(shi(u1.x), c1, a1);
        a2 = fmaf(slo(u1.y), c1, a2); a3 = fmaf(shi(u1.y), c1, a3);
        a0 = fmaf(slo(u2.x), c2, a0); a1 = fmaf(shi(u2.x), c2, a1);
        a2 = fmaf(slo(u2.y), c2, a2); a3 = fmaf(shi(u2.y), c2, a3);
        a0 = fmaf(slo(u3.x), c3, a0); a1 = fmaf(shi(u3.x), c3, a1);
        a2 = fmaf(slo(u3.y), c3, a2); a3 = fmaf(shi(u3.y), c3, a3);
    }
    for (; i < end; ++i) {
        int s0 = g_csr[i];
        float c0 = Ys[s0];
        uint2 u0 = *(const uint2*)(Yq + (size_t)s0 * FH + lo4);
        a0 = fmaf(slo(u0.x), c0, a0); a1 = fmaf(shi(u0.x), c0, a1);
        a2 = fmaf(slo(u0.y), c0, a2); a3 = fmaf(shi(u0.y), c0, a3);
    }
    float dv = g_dinv[w];
    float dv2 = dv * dv;
    float p0, p1, p2, p3;
    if (MODE == 1) {
        float m = -dv2;
        p0 = m * a0; p1 = m * a1; p2 = m * a2; p3 = m * a3;
    } else {
        float xs = X0s[w];
        uint2 xq = *(const uint2*)(X0q + (size_t)w * FH + lo4);
        float m = -2.f * dv2;
        p0 = fmaf(m, a0, -slo(xq.x) * xs);
        p1 = fmaf(m, a1, -shi(xq.x) * xs);
        p2 = fmaf(m, a2, -slo(xq.y) * xs);
        p3 = fmaf(m, a3, -shi(xq.y) * xs);
    }
    float mx = fmaxf(fmaxf(fabsf(p0), fabsf(p1)), fmaxf(fabsf(p2), fabsf(p3)));
    #pragma unroll
    for (int o = 16; o >= 1; o >>= 1) mx = fmaxf(mx, __shfl_xor_sync(0xffffffffu, mx, o));
    float sinv = (mx > 0.f) ? (32766.f / mx) : 0.f;
    uint2 q;
    q.x = packs16(p0, p1, sinv);
    q.y = packs16(p2, p3, sinv);
    *(uint2*)(oq + (size_t)w * FH + lo4) = q;
    if (lane == 0) os[w] = mx * (1.f / 32766.f);
}

// ======================= pipelined mma.sync GEMM, int16 A with smem dequant ======
// (exact R7 champion version — smem dequant pass shared across warps)
#define GS_SCR 0
#define GS_AHI 16384
#define GS_ALO 32768
#define GS_BHI 49152
#define GS_BLO 65536
#define GS_ST  81920
#define GM_SMEM_SZ (2 * GS_ST)

__global__ void __launch_bounds__(512) k_gemm_mma(
    const unsigned short* __restrict__ x0q, const float* __restrict__ x0s,
    const float* __restrict__ bias,
    const __nv_bfloat16* __restrict__ wth, const __nv_bfloat16* __restrict__ wtl,
    unsigned short* __restrict__ outq, float* __restrict__ outs) {
    extern __shared__ char smem_raw[];
    __shared__ float s_bias[128];
    __shared__ float s_scl[3][128];
    __shared__ float s_rmax[128][4];
    uint32_t sb0 = smem_u32(smem_raw);
    uint32_t sb = (sb0 + 1023u) & ~1023u;          // 1024B-align for SW128
    char* smc = smem_raw + (sb - sb0);

    const int tid = threadIdx.x, lane = tid & 31, wid = tid >> 5;
    const int wm = wid >> 2, wn = wid & 3;         // 4x4 warp grid
    const int rowBase = blockIdx.x * 128;

    const unsigned short* Aq[3] = {x0q, g_I1, g_I2};
    const float* Sq[3] = {x0s, g_S1, g_S2};
    if (tid < 128) {
        s_bias[tid] = bias[tid];
        int row = rowBase + tid;
        bool ok = row < NN;
        #pragma unroll
        for (int b = 0; b < 3; ++b)
            s_scl[b][tid] = ok ? Sq[b][row] : 0.f;
    }
    __syncthreads();

    float acc[2][4][4];
    #pragma unroll
    for (int a = 0; a < 2; ++a)
        #pragma unroll
        for (int b = 0; b < 4; ++b)
            #pragma unroll
            for (int c = 0; c < 4; ++c) acc[a][b][c] = 0.f;

    const int lrow = lane & 7, seg = lane >> 3;

    auto load_chunk = [&](uint32_t st, int kc) {
        const int coff = (kc & 1) * 64;
        const unsigned short* __restrict__ aq = Aq[kc >> 1];
        #pragma unroll
        for (int t = 0; t < 2; ++t) {
            int idx = tid + t * 512;
            int r = idx >> 3, j = idx & 7;
            int row = rowBase + r;
            bool ok = row < NN;
            int rowc = ok ? row : (NN - 1);
            cpa16(st + GS_SCR + (uint32_t)(r * 128 + j * 16),
                  aq + (size_t)rowc * FH + coff + j * 8, ok);
        }
        #pragma unroll
        for (int t = 0; t < 2; ++t) {
            int idx = tid + t * 512;
            int n = idx >> 3, j = idx & 7;
            uint32_t sw = SWZ((uint32_t)(n * 128 + j * 16));
            cpa16(st + GS_BHI + sw, wth + (size_t)n * 384 + kc * 64 + j * 8, true);
            cpa16(st + GS_BLO + sw, wtl + (size_t)n * 384 + kc * 64 + j * 8, true);
        }
    };

    load_chunk(sb, 0);
    CP_COMMIT();

    #pragma unroll 1
    for (int kc = 0; kc < 6; ++kc) {
        if (kc < 5) {
            load_chunk(sb + (((kc + 1) & 1) ? GS_ST : 0), kc + 1);
            CP_COMMIT();
            CP_WAIT(1);
        } else {
            CP_WAIT(0);
        }
        __syncthreads();

        const uint32_t st = sb + ((kc & 1) ? GS_ST : 0);
        char* stc = smc + ((kc & 1) ? GS_ST : 0);
        // dequant scratch int16 -> A hi/lo bf16 planes (once per element, all warps share)
        {
            const float* sc = s_scl[kc >> 1];
            #pragma unroll
            for (int t = 0; t < 2; ++t) {
                int idx = tid + t * 512;
                int r = idx >> 3, j = idx & 7;
                uint4 u = *(const uint4*)(stc + GS_SCR + (uint32_t)(r * 128 + j * 16));
                float s = sc[r];
                float v0 = slo(u.x) * s, v1 = shi(u.x) * s;
                float v2 = slo(u.y) * s, v3 = shi(u.y) * s;
                float v4 = slo(u.z) * s, v5 = shi(u.z) * s;
                float v6 = slo(u.w) * s, v7 = shi(u.w) * s;
                uint4 h, l;
                h.x = pack_hi2(v0, v1); l.x = pack_lo2(v0, v1);
                h.y = pack_hi2(v2, v3); l.y = pack_lo2(v2, v3);
                h.z = pack_hi2(v4, v5); l.z = pack_lo2(v4, v5);
                h.w = pack_hi2(v6, v7); l.w = pack_lo2(v6, v7);
                uint32_t sw = SWZ((uint32_t)(r * 128 + j * 16));
                *(uint4*)(stc + GS_AHI + sw) = h;
                *(uint4*)(stc + GS_ALO + sw) = l;
            }
        }
        __syncthreads();

        #pragma unroll
        for (int kt = 0; kt < 4; ++kt) {
            uint32_t Ahf[2][4], Alf[2][4], Bhf[2][4], Blf[2][4];
            #pragma unroll
            for (int mt = 0; mt < 2; ++mt) {
                int m = wm * 32 + mt * 16 + (seg & 1) * 8 + lrow;
                int kb = kt * 32 + (seg >> 1) * 16;
                uint32_t sw = SWZ((uint32_t)(m * 128 + kb));
                ldmx4(Ahf[mt], st + GS_AHI + sw);
                ldmx4(Alf[mt], st + GS_ALO + sw);
            }
            #pragma unroll
            for (int ntp = 0; ntp < 2; ++ntp) {
                int n = wn * 32 + ntp * 16 + (seg >> 1) * 8 + lrow;
                int kb = kt * 32 + (seg & 1) * 16;
                uint32_t sw = SWZ((uint32_t)(n * 128 + kb));
                ldmx4(Bhf[ntp], st + GS_BHI + sw);
                ldmx4(Blf[ntp], st + GS_BLO + sw);
            }
            #pragma unroll
            for (int mt = 0; mt < 2; ++mt)
                #pragma unroll
                for (int ntp = 0; ntp < 2; ++ntp)
                    #pragma unroll
                    for (int sub = 0; sub < 2; ++sub) {
                        int nj = ntp * 2 + sub;
                        mma_bf16(acc[mt][nj], Ahf[mt], &Bhf[ntp][sub * 2]);
                        mma_bf16(acc[mt][nj], Ahf[mt], &Blf[ntp][sub * 2]);
                        mma_bf16(acc[mt][nj], Alf[mt], &Bhf[ntp][sub * 2]);
                    }
        }
        __syncthreads();
    }

    // ---- epilogue: p = relu(acc*rdinv + b)*dinv; rowmax-quantize to int16 ----
    float dvr[2][2], rdr[2][2];
    #pragma unroll
    for (int mt = 0; mt < 2; ++mt)
        #pragma unroll
        for (int rp = 0; rp < 2; ++rp) {
            int row = rowBase + wm * 32 + mt * 16 + (lane >> 2) + rp * 8;
            bool ok = row < NN;
            dvr[mt][rp] = ok ? g_dinv[row] : 0.f;
            rdr[mt][rp] = ok ? g_rdinv[row] : 0.f;
        }
    float pm[2][2] = {{0.f, 0.f}, {0.f, 0.f}};
    #pragma unroll
    for (int mt = 0; mt < 2; ++mt)
        #pragma unroll
        for (int nj = 0; nj < 4; ++nj) {
            int col = wn * 32 + nj * 8 + (lane & 3) * 2;
            float bz0 = s_bias[col], bz1 = s_bias[col + 1];
            #pragma unroll
            for (int rp = 0; rp < 2; ++rp) {
                float rd = rdr[mt][rp], dv = dvr[mt][rp];
                float p0 = fmaxf(fmaf(acc[mt][nj][rp * 2 + 0], rd, bz0), 0.f) * dv;
                float p1 = fmaxf(fmaf(acc[mt][nj][rp * 2 + 1], rd, bz1), 0.f) * dv;
                pm[mt][rp] = fmaxf(pm[mt][rp], fmaxf(p0, p1));
            }
        }
    #pragma unroll
    for (int mt = 0; mt < 2; ++mt)
        #pragma unroll
        for (int rp = 0; rp < 2; ++rp) {
            float m = pm[mt][rp];
            m = fmaxf(m, __shfl_xor_sync(0xffffffffu, m, 1));
            m = fmaxf(m, __shfl_xor_sync(0xffffffffu, m, 2));
            if ((lane & 3) == 0)
                s_rmax[wm * 32 + mt * 16 + rp * 8 + (lane >> 2)][wn] = m;
        }
    __syncthreads();
    #pragma unroll
    for (int mt = 0; mt < 2; ++mt)
        #pragma unroll
        for (int rp = 0; rp < 2; ++rp) {
            int rl = wm * 32 + mt * 16 + rp * 8 + (lane >> 2);
            int row = rowBase + rl;
            float rm = fmaxf(fmaxf(s_rmax[rl][0], s_rmax[rl][1]),
                             fmaxf(s_rmax[rl][2], s_rmax[rl][3]));
            float sinv = (rm > 0.f) ? (32766.f / rm) : 0.f;
            if (wn == 0 && (lane & 3) == 0 && row < NN)
                outs[row] = rm * (1.f / 32766.f);
            if (row < NN) {
                float rd = rdr[mt][rp], dv = dvr[mt][rp];
                #pragma unroll
                for (int nj = 0; nj < 4; ++nj) {
                    int col = wn * 32 + nj * 8 + (lane & 3) * 2;
                    float bz0 = s_bias[col], bz1 = s_bias[col + 1];
                    float p0 = fmaxf(fmaf(acc[mt][nj][rp * 2 + 0], rd, bz0), 0.f) * dv;
                    float p1 = fmaxf(fmaf(acc[mt][nj][rp * 2 + 1], rd, bz1), 0.f) * dv;
                    *(uint32_t*)(outq + (size_t)row * FH + col) = packs16(p0, p1, sinv);
                }
            }
        }
}

// ======================= SIMT GEMM for final layer (CO=40) =======================
template <int CO, int TM, int TN>
__global__ void k_gemm_simt(
    const unsigned short* __restrict__ X0q, const float* __restrict__ X0s,
    const unsigned short* __restrict__ X1q, const float* __restrict__ X1s,
    const unsigned short* __restrict__ X2q, const float* __restrict__ X2s,
    const float* __restrict__ W, const float* __restrict__ bias,
    float* __restrict__ out) {
    constexpr int BM = 128, BK = 16;
    constexpr int NTX = CO / TN;
    constexpr int NTY = BM / TM;
    constexpr int NT = NTX * NTY;
    __shared__ float As[BK][BM + 1];
    __shared__ float Bs[BK][CO];
    const int tid = threadIdx.x;
    const int tx = tid % NTX;
    const int ty = tid / NTX;
    const int rowBase = blockIdx.x * BM;

    float acc[TM][TN];
    #pragma unroll
    for (int m = 0; m < TM; ++m)
        #pragma unroll
        for (int n = 0; n < TN; ++n) acc[m][n] = 0.f;

    #pragma unroll 1
    for (int kt = 0; kt < 24; ++kt) {
        const unsigned short* __restrict__ Xq = (kt < 8) ? X0q : ((kt < 16) ? X1q : X2q);
        const float* __restrict__ Xs = (kt < 8) ? X0s : ((kt < 16) ? X1s : X2s);
        const int kcol = (kt & 7) * BK;
        for (int i = tid; i < BM * BK; i += NT) {
            int r = i >> 4, k = i & 15;
            int row = rowBase + r;
            float v = 0.f;
            if (row < NN) {
                size_t off = (size_t)row * FH + kcol + k;
                v = (float)(short)Xq[off] * Xs[row] * g_rdinv[row];
            }
            As[k][r] = v;
        }
        for (int i = tid; i < BK * CO; i += NT) {
            int k = i / CO, c = i % CO;
            Bs[k][c] = W[(size_t)(kt * BK + k) * CO + c];
        }
        __syncthreads();
        #pragma unroll
        for (int k = 0; k < BK; ++k) {
            float ra[TM], rb[TN];
            #pragma unroll
            for (int m = 0; m < TM; ++m) ra[m] = As[k][ty * TM + m];
            #pragma unroll
            for (int n = 0; n < TN; ++n) rb[n] = Bs[k][tx * TN + n];
            #pragma unroll
            for (int m = 0; m < TM; ++m)
                #pragma unroll
                for (int n = 0; n < TN; ++n)
                    acc[m][n] = fmaf(ra[m], rb[n], acc[m][n]);
        }
        __syncthreads();
    }
    #pragma unroll
    for (int m = 0; m < TM; ++m) {
        int row = rowBase + ty * TM + m;
        if (row < NN) {
            #pragma unroll
            for (int n = 0; n < TN; ++n) {
                int c = tx * TN + n;
                out[(size_t)row * CO + c] = fmaxf(acc[m][n] + bias[c], 0.f);
            }
        }
    }
}

// ======================= host launcher =======================
extern "C" void kernel_launch(void* const* d_in, const int* in_sizes, int n_in,
                              void* d_out, int out_size) {
    const float* feat = (const float*)d_in[0];
    const int*   src  = (const int*)d_in[1];
    const int*   dst  = (const int*)d_in[2];
    const float* W0   = (const float*)d_in[3];
    const float* b0   = (const float*)d_in[4];
    const float* Wh   = (const float*)d_in[5];
    const float* bh   = (const float*)d_in[6];
    const float* Wl   = (const float*)d_in[7];
    const float* bl   = (const float*)d_in[8];
    float* out = (float*)d_out;

    unsigned short *I0, *I1, *I2;
    float *S0, *S1, *S2;
    __nv_bfloat16 *Wth, *Wtl;
    int* degp;
    cudaGetSymbolAddress((void**)&I0,  g_I0);
    cudaGetSymbolAddress((void**)&I1,  g_I1);
    cudaGetSymbolAddress((void**)&I2,  g_I2);
    cudaGetSymbolAddress((void**)&S0,  g_S0);
    cudaGetSymbolAddress((void**)&S1,  g_S1);
    cudaGetSymbolAddress((void**)&S2,  g_S2);
    cudaGetSymbolAddress((void**)&Wth, g_Wth);
    cudaGetSymbolAddress((void**)&Wtl, g_Wtl);
    cudaGetSymbolAddress((void**)&degp, g_deg);

    cudaFuncSetAttribute(k_gemm_mma, cudaFuncAttributeMaxDynamicSharedMemorySize,
                         GM_SMEM_SZ + 1024);

    const int TPB = 256;
    const int nodeBlocks = (NN + TPB - 1) / TPB;
    const int edgeBlocks = (NE + TPB - 1) / TPB;
    const int scanBlocks = (NN + 1023) / 1024;   // 98

    // preprocessing
    cudaMemsetAsync(degp, 0, NN * sizeof(int));
    k_hist<<<edgeBlocks, TPB>>>(dst);
    k_scanA<<<scanBlocks, 1024>>>();
    k_scanB<<<1, 128>>>(scanBlocks);
    k_scanC<<<nodeBlocks, TPB>>>();   // + dinv/rdinv
    k_scatter<<<edgeBlocks, TPB>>>(src, dst);

    // input conversion (warp per row)
    k_featsplit<<<(NN * 32 + TPB - 1) / TPB, TPB>>>(feat);
    k_prep_w<<<(6 * 384 * 128 + TPB - 1) / TPB, TPB>>>(W0, Wh);

    const size_t SL = (size_t)NN * FH;
    const int spmmBlocks = (NN * 32 + TPB - 1) / TPB;
    const int tileBlocks = (NN + 127) / 128;

    int cur = 0;
    for (int l = 0; l < 7; ++l) {
        const unsigned short* I0c = I0 + (size_t)cur * SL;
        const float* S0c = S0 + (size_t)cur * NN;
        k_spmm<1><<<spmmBlocks, TPB>>>(I0c, S0c, nullptr, nullptr, I1, S1);
        k_spmm<2><<<spmmBlocks, TPB>>>(I1, S1, I0c, S0c, I2, S2);
        if (l < 6) {
            const float* bias = (l == 0) ? b0 : (bh + (size_t)(l - 1) * 128);
            int nxt = 1 - cur;
            k_gemm_mma<<<tileBlocks, 512, GM_SMEM_SZ + 1024>>>(
                I0c, S0c, bias,
                Wth + (size_t)l * 128 * 384, Wtl + (size_t)l * 128 * 384,
                I0 + (size_t)nxt * SL, S0 + (size_t)nxt * NN);
            cur = nxt;
        } else {
            k_gemm_simt<FO, 8, 5><<<tileBlocks, 128>>>(
                I0c, S0c, I1, S1, I2, S2, Wl, bl, out);
        }
    }
}

// round 12
// speedup vs baseline: 1.6254x; 1.4387x over previous
#include <cuda_runtime.h>
#include <cuda_fp16.h>
#include <cstdint>

#define NN 100000
#define NE 1600000
#define FH 128
#define FO 40

// ======================= device scratch (no allocs allowed) =======================
__device__ int   g_deg[NN];
__device__ float g_dinv[NN];
__device__ float g_rdinv[NN];
__device__ int   g_rowoff[NN + 1];
__device__ int   g_cursor[NN];
__device__ int   g_csr[NE];
__device__ int   g_bsum[128];
__device__ int   g_boff[128];

// prescaled (x*dinv) fp16 activation planes
__device__ __half g_F0[2][(size_t)NN * FH];
__device__ __half g_F1[(size_t)NN * FH];
__device__ __half g_F2[(size_t)NN * FH];
// weights: exact f16 hi/lo split of W^T  [n=128][k=384]
__device__ __half g_Wh[6 * 128 * 384];
__device__ __half g_Wl[6 * 128 * 384];

// ======================= helpers =======================
__device__ __forceinline__ uint32_t smem_u32(const void* p) {
    uint32_t a;
    asm("{ .reg .u64 t; cvta.to.shared.u64 t, %1; cvt.u32.u64 %0, t; }" : "=r"(a) : "l"(p));
    return a;
}

#define SWZ(off) ((off) ^ (((off) >> 3) & 0x70))

__device__ __forceinline__ void ldmx4(uint32_t* r, uint32_t addr) {
    asm volatile("ldmatrix.sync.aligned.m8n8.x4.shared.b16 {%0,%1,%2,%3}, [%4];"
                 : "=r"(r[0]), "=r"(r[1]), "=r"(r[2]), "=r"(r[3]) : "r"(addr));
}

__device__ __forceinline__ void mma_f16(float* d, const uint32_t* a, const uint32_t* b) {
    asm volatile(
        "mma.sync.aligned.m16n8k16.row.col.f32.f16.f16.f32 "
        "{%0,%1,%2,%3}, {%4,%5,%6,%7}, {%8,%9}, {%0,%1,%2,%3};"
        : "+f"(d[0]), "+f"(d[1]), "+f"(d[2]), "+f"(d[3])
        : "r"(a[0]), "r"(a[1]), "r"(a[2]), "r"(a[3]), "r"(b[0]), "r"(b[1]));
}

__device__ __forceinline__ void cpa16(uint32_t saddr, const void* g, bool pred) {
    asm volatile("cp.async.cg.shared.global [%0], [%1], 16, %2;"
                 :: "r"(saddr), "l"(g), "r"(pred ? 16 : 0) : "memory");
}
#define CP_COMMIT() asm volatile("cp.async.commit_group;" ::: "memory")
#define CP_WAIT(n)  asm volatile("cp.async.wait_group %0;" :: "n"(n) : "memory")

__device__ __forceinline__ float2 h2f2(uint32_t u) {
    __half2 h = *reinterpret_cast<__half2*>(&u);
    return __half22float2(h);
}
__device__ __forceinline__ uint32_t f2h2(float a, float b) {
    __half2 h = __floats2half2_rn(a, b);
    return *reinterpret_cast<uint32_t*>(&h);
}

// ======================= graph preprocessing =======================
__global__ void k_hist(const int* __restrict__ dst) {
    int e = blockIdx.x * blockDim.x + threadIdx.x;
    if (e < NE) atomicAdd(&g_deg[dst[e]], 1);
}

__global__ void __launch_bounds__(1024) k_scanA() {
    __shared__ int wsum[32];
    int t = threadIdx.x, lane = t & 31, wp = t >> 5;
    int i = blockIdx.x * 1024 + t;
    int v = (i < NN) ? g_deg[i] : 0;
    int x = v;
    #pragma unroll
    for (int o = 1; o < 32; o <<= 1) {
        int y = __shfl_up_sync(0xffffffffu, x, o);
        if (lane >= o) x += y;
    }
    if (lane == 31) wsum[wp] = x;
    __syncthreads();
    if (wp == 0) {
        int s = wsum[lane];
        #pragma unroll
        for (int o = 1; o < 32; o <<= 1) {
            int y = __shfl_up_sync(0xffffffffu, s, o);
            if (lane >= o) s += y;
        }
        wsum[lane] = s;
    }
    __syncthreads();
    int off = (wp ? wsum[wp - 1] : 0);
    if (i < NN) g_rowoff[i] = off + x - v;
    if (t == 1023) g_bsum[blockIdx.x] = wsum[31];
}

__global__ void k_scanB(int nb) {
    __shared__ int sh[4];
    int t = threadIdx.x, lane = t & 31, wp = t >> 5;
    int v = (t < nb) ? g_bsum[t] : 0;
    int x = v;
    #pragma unroll
    for (int o = 1; o < 32; o <<= 1) {
        int y = __shfl_up_sync(0xffffffffu, x, o);
        if (lane >= o) x += y;
    }
    if (lane == 31) sh[wp] = x;
    __syncthreads();
    int add = 0;
    for (int w = 0; w < wp; ++w) add += sh[w];
    if (t < 128) g_boff[t] = add + x - v;
}

// scanC + dinv fused
__global__ void k_scanC() {
    int i = blockIdx.x * blockDim.x + threadIdx.x;
    if (i < NN) {
        int r = g_rowoff[i] + g_boff[i >> 10];
        g_rowoff[i] = r;
        g_cursor[i] = r;
        int d = g_deg[i];
        float df = (float)(d > 1 ? d : 1);
        g_dinv[i] = rsqrtf(df);
        g_rdinv[i] = sqrtf(df);
    }
    if (i == 0) g_rowoff[NN] = NE;
}

__global__ void k_scatter(const int* __restrict__ src, const int* __restrict__ dst) {
    int e = blockIdx.x * blockDim.x + threadIdx.x;
    if (e < NE) {
        int p = atomicAdd(&g_cursor[dst[e]], 1);
        g_csr[p] = src[e];
    }
}

// ======================= input conversion =======================
__global__ void k_featsplit(const float* __restrict__ f) {
    size_t i = ((size_t)blockIdx.x * blockDim.x + threadIdx.x) * 4;
    if (i >= (size_t)NN * FH) return;
    int row = (int)(i >> 7);
    float dv = g_dinv[row];
    float4 v = *(const float4*)(f + i);
    uint2 q;
    q.x = f2h2(v.x * dv, v.y * dv);
    q.y = f2h2(v.z * dv, v.w * dv);
    *(uint2*)(&g_F0[0][i]) = q;
}

__global__ void k_prep_w(const float* __restrict__ W0, const float* __restrict__ Wh) {
    int i = blockIdx.x * blockDim.x + threadIdx.x;
    if (i >= 6 * 384 * 128) return;
    int l = i / (384 * 128);
    int r = i % (384 * 128);
    int k = r / 128, n = r % 128;
    const float* W = (l == 0) ? W0 : (Wh + (size_t)(l - 1) * 384 * 128);
    float v = W[(size_t)k * 128 + n];
    __half h = __float2half_rn(v);
    float lo = v - __half2float(h);
    size_t o = (size_t)l * 128 * 384 + (size_t)n * 384 + k;
    g_Wh[o] = h;
    g_Wl[o] = __float2half_rn(lo);
}

// ======================= SpMM: warp-per-node CSR gather, fp16 in/out ============
// All planes prescaled by dinv. MODE 1: X1p = -dv^2*sum  MODE 2: X2p = -2dv^2*sum - X0p
template <int MODE>
__global__ void __launch_bounds__(256) k_spmm(
    const __half* __restrict__ Y,
    const __half* __restrict__ X0,
    __half* __restrict__ o) {
    int w = (blockIdx.x * blockDim.x + threadIdx.x) >> 5;
    int lane = threadIdx.x & 31;
    if (w >= NN) return;
    int beg = g_rowoff[w];
    int end = g_rowoff[w + 1];
    const size_t lo4 = (size_t)(lane * 4);
    float a0 = 0.f, a1 = 0.f, a2 = 0.f, a3 = 0.f;
    int i = beg;
    for (; i + 4 <= end; i += 4) {
        int s0 = g_csr[i], s1 = g_csr[i + 1], s2 = g_csr[i + 2], s3 = g_csr[i + 3];
        uint2 u0 = *(const uint2*)(Y + (size_t)s0 * FH + lo4);
        uint2 u1 = *(const uint2*)(Y + (size_t)s1 * FH + lo4);
        uint2 u2 = *(const uint2*)(Y + (size_t)s2 * FH + lo4);
        uint2 u3 = *(const uint2*)(Y + (size_t)s3 * FH + lo4);
        float2 f;
        f = h2f2(u0.x); a0 += f.x; a1 += f.y;
        f = h2f2(u0.y); a2 += f.x; a3 += f.y;
        f = h2f2(u1.x); a0 += f.x; a1 += f.y;
        f = h2f2(u1.y); a2 += f.x; a3 += f.y;
        f = h2f2(u2.x); a0 += f.x; a1 += f.y;
        f = h2f2(u2.y); a2 += f.x; a3 += f.y;
        f = h2f2(u3.x); a0 += f.x; a1 += f.y;
        f = h2f2(u3.y); a2 += f.x; a3 += f.y;
    }
    for (; i < end; ++i) {
        int s0 = g_csr[i];
        uint2 u0 = *(const uint2*)(Y + (size_t)s0 * FH + lo4);
        float2 f;
        f = h2f2(u0.x); a0 += f.x; a1 += f.y;
        f = h2f2(u0.y); a2 += f.x; a3 += f.y;
    }
    float dv = g_dinv[w];
    float dv2 = dv * dv;
    float p0, p1, p2, p3;
    if (MODE == 1) {
        float m = -dv2;
        p0 = m * a0; p1 = m * a1; p2 = m * a2; p3 = m * a3;
    } else {
        uint2 xq = *(const uint2*)(X0 + (size_t)w * FH + lo4);
        float2 x0 = h2f2(xq.x), x1 = h2f2(xq.y);
        float m = -2.f * dv2;
        p0 = fmaf(m, a0, -x0.x);
        p1 = fmaf(m, a1, -x0.y);
        p2 = fmaf(m, a2, -x1.x);
        p3 = fmaf(m, a3, -x1.y);
    }
    uint2 q;
    q.x = f2h2(p0, p1);
    q.y = f2h2(p2, p3);
    *(uint2*)(o + (size_t)w * FH + lo4) = q;
}

// ======================= pipelined mma.sync GEMM, fp16 A, f16-pair weights ======
// C = relu( rdinv[m] * ([X0p|X1p|X2p] @ (Wh+Wl)) + b ); store (C*dinv[m]) fp16.
// Per stage: A 16K | B_hi 16K | B_lo 16K = 48K; x2 stages = 96K.
#define GS_A   0
#define GS_BHI 16384
#define GS_BLO 32768
#define GS_ST  49152
#define GM_SMEM_SZ (2 * GS_ST)

__global__ void __launch_bounds__(512, 2) k_gemm_mma(
    const __half* __restrict__ x0,
    const float* __restrict__ bias,
    const __half* __restrict__ wh, const __half* __restrict__ wl,
    __half* __restrict__ outp) {
    extern __shared__ char smem_raw[];
    __shared__ float s_bias[128];
    uint32_t sb0 = smem_u32(smem_raw);
    uint32_t sb = (sb0 + 1023u) & ~1023u;          // 1024B-align for SW128

    const int tid = threadIdx.x, lane = tid & 31, wid = tid >> 5;
    const int wm = wid >> 2, wn = wid & 3;         // 4x4 warp grid
    const int rowBase = blockIdx.x * 128;
    if (tid < 128) s_bias[tid] = bias[tid];
    __syncthreads();

    const __half* Ap[3] = {x0, g_F1, g_F2};

    float acc[2][4][4];
    #pragma unroll
    for (int a = 0; a < 2; ++a)
        #pragma unroll
        for (int b = 0; b < 4; ++b)
            #pragma unroll
            for (int c = 0; c < 4; ++c) acc[a][b][c] = 0.f;

    const int lrow = lane & 7, seg = lane >> 3;

    auto load_chunk = [&](uint32_t st, int kc) {
        const int coff = (kc & 1) * 64;
        const __half* __restrict__ ap = Ap[kc >> 1];
        #pragma unroll
        for (int t = 0; t < 2; ++t) {
            int idx = tid + t * 512;
            int r = idx >> 3, j = idx & 7;
            int row = rowBase + r;
            bool ok = row < NN;
            int rowc = ok ? row : (NN - 1);
            uint32_t sw = SWZ((uint32_t)(r * 128 + j * 16));
            cpa16(st + GS_A + sw, ap + (size_t)rowc * FH + coff + j * 8, ok);
        }
        #pragma unroll
        for (int t = 0; t < 2; ++t) {
            int idx = tid + t * 512;
            int n = idx >> 3, j = idx & 7;
            uint32_t sw = SWZ((uint32_t)(n * 128 + j * 16));
            cpa16(st + GS_BHI + sw, wh + (size_t)n * 384 + kc * 64 + j * 8, true);
            cpa16(st + GS_BLO + sw, wl + (size_t)n * 384 + kc * 64 + j * 8, true);
        }
    };

    load_chunk(sb, 0);
    CP_COMMIT();

    #pragma unroll 1
    for (int kc = 0; kc < 6; ++kc) {
        if (kc < 5) {
            load_chunk(sb + (((kc + 1) & 1) ? GS_ST : 0), kc + 1);
            CP_COMMIT();
            CP_WAIT(1);
        } else {
            CP_WAIT(0);
        }
        __syncthreads();

        const uint32_t st = sb + ((kc & 1) ? GS_ST : 0);
        #pragma unroll
        for (int kt = 0; kt < 4; ++kt) {
            uint32_t Af[2][4], Bhf[2][4], Blf[2][4];
            #pragma unroll
            for (int mt = 0; mt < 2; ++mt) {
                int m = wm * 32 + mt * 16 + (seg & 1) * 8 + lrow;
                int kb = kt * 32 + (seg >> 1) * 16;
                uint32_t sw = SWZ((uint32_t)(m * 128 + kb));
                ldmx4(Af[mt], st + GS_A + sw);
            }
            #pragma unroll
            for (int ntp = 0; ntp < 2; ++ntp) {
                int n = wn * 32 + ntp * 16 + (seg >> 1) * 8 + lrow;
                int kb = kt * 32 + (seg & 1) * 16;
                uint32_t sw = SWZ((uint32_t)(n * 128 + kb));
                ldmx4(Bhf[ntp], st + GS_BHI + sw);
                ldmx4(Blf[ntp], st + GS_BLO + sw);
            }
            #pragma unroll
            for (int mt = 0; mt < 2; ++mt)
                #pragma unroll
                for (int ntp = 0; ntp < 2; ++ntp)
                    #pragma unroll
                    for (int sub = 0; sub < 2; ++sub) {
                        int nj = ntp * 2 + sub;
                        mma_f16(acc[mt][nj], Af[mt], &Bhf[ntp][sub * 2]);
                        mma_f16(acc[mt][nj], Af[mt], &Blf[ntp][sub * 2]);
                    }
        }
        __syncthreads();
    }

    // ---- epilogue: p = relu(acc*rdinv + b)*dinv; write fp16 ----
    #pragma unroll
    for (int mt = 0; mt < 2; ++mt) {
        #pragma unroll
        for (int rp = 0; rp < 2; ++rp) {
            int row = rowBase + wm * 32 + mt * 16 + (lane >> 2) + rp * 8;
            if (row < NN) {
                float dv = g_dinv[row], rd = g_rdinv[row];
                #pragma unroll
                for (int nj = 0; nj < 4; ++nj) {
                    int col = wn * 32 + nj * 8 + (lane & 3) * 2;
                    float bz0 = s_bias[col], bz1 = s_bias[col + 1];
                    float p0 = fmaxf(fmaf(acc[mt][nj][rp * 2 + 0], rd, bz0), 0.f) * dv;
                    float p1 = fmaxf(fmaf(acc[mt][nj][rp * 2 + 1], rd, bz1), 0.f) * dv;
                    *(uint32_t*)(outp + (size_t)row * FH + col) = f2h2(p0, p1);
                }
            }
        }
    }
}

// ======================= SIMT GEMM for final layer (CO=40) =======================
// bases reconstructed from fp16 planes: x = h * rdinv.
template <int CO, int TM, int TN>
__global__ void k_gemm_simt(
    const __half* __restrict__ X0, const __half* __restrict__ X1,
    const __half* __restrict__ X2,
    const float* __restrict__ W, const float* __restrict__ bias,
    float* __restrict__ out) {
    constexpr int BM = 128, BK = 16;
    constexpr int NTX = CO / TN;
    constexpr int NTY = BM / TM;
    constexpr int NT = NTX * NTY;
    __shared__ float As[BK][BM + 1];
    __shared__ float Bs[BK][CO];
    const int tid = threadIdx.x;
    const int tx = tid % NTX;
    const int ty = tid / NTX;
    const int rowBase = blockIdx.x * BM;

    float acc[TM][TN];
    #pragma unroll
    for (int m = 0; m < TM; ++m)
        #pragma unroll
        for (int n = 0; n < TN; ++n) acc[m][n] = 0.f;

    #pragma unroll 1
    for (int kt = 0; kt < 24; ++kt) {
        const __half* __restrict__ X = (kt < 8) ? X0 : ((kt < 16) ? X1 : X2);
        const int kcol = (kt & 7) * BK;
        for (int i = tid; i < BM * BK; i += NT) {
            int r = i >> 4, k = i & 15;
            int row = rowBase + r;
            float v = 0.f;
            if (row < NN) {
                size_t off = (size_t)row * FH + kcol + k;
                v = __half2float(X[off]) * g_rdinv[row];
            }
            As[k][r] = v;
        }
        for (int i = tid; i < BK * CO; i += NT) {
            int k = i / CO, c = i % CO;
            Bs[k][c] = W[(size_t)(kt * BK + k) * CO + c];
        }
        __syncthreads();
        #pragma unroll
        for (int k = 0; k < BK; ++k) {
            float ra[TM], rb[TN];
            #pragma unroll
            for (int m = 0; m < TM; ++m) ra[m] = As[k][ty * TM + m];
            #pragma unroll
            for (int n = 0; n < TN; ++n) rb[n] = Bs[k][tx * TN + n];
            #pragma unroll
            for (int m = 0; m < TM; ++m)
                #pragma unroll
                for (int n = 0; n < TN; ++n)
                    acc[m][n] = fmaf(ra[m], rb[n], acc[m][n]);
        }
        __syncthreads();
    }
    #pragma unroll
    for (int m = 0; m < TM; ++m) {
        int row = rowBase + ty * TM + m;
        if (row < NN) {
            #pragma unroll
            for (int n = 0; n < TN; ++n) {
                int c = tx * TN + n;
                out[(size_t)row * CO + c] = fmaxf(acc[m][n] + bias[c], 0.f);
            }
        }
    }
}

// ======================= host launcher =======================
extern "C" void kernel_launch(void* const* d_in, const int* in_sizes, int n_in,
                              void* d_out, int out_size) {
    const float* feat = (const float*)d_in[0];
    const int*   src  = (const int*)d_in[1];
    const int*   dst  = (const int*)d_in[2];
    const float* W0   = (const float*)d_in[3];
    const float* b0   = (const float*)d_in[4];
    const float* Wh_  = (const float*)d_in[5];
    const float* bh   = (const float*)d_in[6];
    const float* Wl_  = (const float*)d_in[7];
    const float* bl   = (const float*)d_in[8];
    float* out = (float*)d_out;

    __half *F0, *F1, *F2, *Wh, *Wl;
    int* degp;
    cudaGetSymbolAddress((void**)&F0, g_F0);
    cudaGetSymbolAddress((void**)&F1, g_F1);
    cudaGetSymbolAddress((void**)&F2, g_F2);
    cudaGetSymbolAddress((void**)&Wh, g_Wh);
    cudaGetSymbolAddress((void**)&Wl, g_Wl);
    cudaGetSymbolAddress((void**)&degp, g_deg);

    cudaFuncSetAttribute(k_gemm_mma, cudaFuncAttributeMaxDynamicSharedMemorySize,
                         GM_SMEM_SZ + 1024);

    const int TPB = 256;
    const int nodeBlocks = (NN + TPB - 1) / TPB;
    const int edgeBlocks = (NE + TPB - 1) / TPB;
    const int scanBlocks = (NN + 1023) / 1024;   // 98

    // preprocessing
    cudaMemsetAsync(degp, 0, NN * sizeof(int));
    k_hist<<<edgeBlocks, TPB>>>(dst);
    k_scanA<<<scanBlocks, 1024>>>();
    k_scanB<<<1, 128>>>(scanBlocks);
    k_scanC<<<nodeBlocks, TPB>>>();   // + dinv/rdinv
    k_scatter<<<edgeBlocks, TPB>>>(src, dst);

    // input conversion
    k_featsplit<<<(NN * FH / 4 + TPB - 1) / TPB, TPB>>>(feat);
    k_prep_w<<<(6 * 384 * 128 + TPB - 1) / TPB, TPB>>>(W0, Wh_);

    const size_t SL = (size_t)NN * FH;
    const int spmmBlocks = (NN * 32 + TPB - 1) / TPB;
    const int tileBlocks = (NN + 127) / 128;

    int cur = 0;
    for (int l = 0; l < 7; ++l) {
        const __half* F0c = F0 + (size_t)cur * SL;
        k_spmm<1><<<spmmBlocks, TPB>>>(F0c, nullptr, F1);
        k_spmm<2><<<spmmBlocks, TPB>>>(F1, F0c, F2);
        if (l < 6) {
            const float* bias = (l == 0) ? b0 : (bh + (size_t)(l - 1) * 128);
            int nxt = 1 - cur;
            k_gemm_mma<<<tileBlocks, 512, GM_SMEM_SZ + 1024>>>(
                F0c, bias,
                Wh + (size_t)l * 128 * 384, Wl + (size_t)l * 128 * 384,
                F0 + (size_t)nxt * SL);
            cur = nxt;
        } else {
            k_gemm_simt<FO, 8, 5><<<tileBlocks, 128>>>(
                F0c, F1, F2, Wl_, bl, out);
        }
    }
}

// round 13
// speedup vs baseline: 1.8093x; 1.1132x over previous
#include <cuda_runtime.h>
#include <cuda_fp16.h>
#include <cstdint>

#define NN 100000
#define NE 1600000
#define FH 128
#define FO 40

// ======================= device scratch (no allocs allowed) =======================
__device__ int   g_deg[NN];
__device__ float g_dinv[NN];
__device__ float g_rdinv[NN];
__device__ int   g_rowoff[NN + 1];
__device__ int   g_cursor[NN];
__device__ int   g_csr[NE];
__device__ int   g_bsum[128];
__device__ int   g_boff[128];

// prescaled (x*dinv) fp16 activation planes
__device__ __half g_F0[2][(size_t)NN * FH];
__device__ __half g_F1[(size_t)NN * FH];
__device__ __half g_F2[(size_t)NN * FH];
// hidden weights: exact f16 hi/lo split of W^T  [n=128][k=384]
__device__ __half g_Wh[6 * 128 * 384];
__device__ __half g_Wl[6 * 128 * 384];
// final weights: exact f16 hi/lo split of Wl^T padded to [n=64][k=384]
__device__ __half g_WFh[64 * 384];
__device__ __half g_WFl[64 * 384];

// ======================= helpers =======================
__device__ __forceinline__ uint32_t smem_u32(const void* p) {
    uint32_t a;
    asm("{ .reg .u64 t; cvta.to.shared.u64 t, %1; cvt.u32.u64 %0, t; }" : "=r"(a) : "l"(p));
    return a;
}

#define SWZ(off) ((off) ^ (((off) >> 3) & 0x70))

__device__ __forceinline__ void ldmx4(uint32_t* r, uint32_t addr) {
    asm volatile("ldmatrix.sync.aligned.m8n8.x4.shared.b16 {%0,%1,%2,%3}, [%4];"
                 : "=r"(r[0]), "=r"(r[1]), "=r"(r[2]), "=r"(r[3]) : "r"(addr));
}

__device__ __forceinline__ void mma_f16(float* d, const uint32_t* a, const uint32_t* b) {
    asm volatile(
        "mma.sync.aligned.m16n8k16.row.col.f32.f16.f16.f32 "
        "{%0,%1,%2,%3}, {%4,%5,%6,%7}, {%8,%9}, {%0,%1,%2,%3};"
        : "+f"(d[0]), "+f"(d[1]), "+f"(d[2]), "+f"(d[3])
        : "r"(a[0]), "r"(a[1]), "r"(a[2]), "r"(a[3]), "r"(b[0]), "r"(b[1]));
}

__device__ __forceinline__ void cpa16(uint32_t saddr, const void* g, bool pred) {
    asm volatile("cp.async.cg.shared.global [%0], [%1], 16, %2;"
                 :: "r"(saddr), "l"(g), "r"(pred ? 16 : 0) : "memory");
}
#define CP_COMMIT() asm volatile("cp.async.commit_group;" ::: "memory")
#define CP_WAIT(n)  asm volatile("cp.async.wait_group %0;" :: "n"(n) : "memory")

__device__ __forceinline__ float2 h2f2(uint32_t u) {
    __half2 h = *reinterpret_cast<__half2*>(&u);
    return __half22float2(h);
}
__device__ __forceinline__ uint32_t f2h2(float a, float b) {
    __half2 h = __floats2half2_rn(a, b);
    return *reinterpret_cast<uint32_t*>(&h);
}

// ======================= graph preprocessing =======================
__global__ void k_hist(const int* __restrict__ dst) {
    int e = blockIdx.x * blockDim.x + threadIdx.x;
    if (e < NE) atomicAdd(&g_deg[dst[e]], 1);
}

__global__ void __launch_bounds__(1024) k_scanA() {
    __shared__ int wsum[32];
    int t = threadIdx.x, lane = t & 31, wp = t >> 5;
    int i = blockIdx.x * 1024 + t;
    int v = (i < NN) ? g_deg[i] : 0;
    int x = v;
    #pragma unroll
    for (int o = 1; o < 32; o <<= 1) {
        int y = __shfl_up_sync(0xffffffffu, x, o);
        if (lane >= o) x += y;
    }
    if (lane == 31) wsum[wp] = x;
    __syncthreads();
    if (wp == 0) {
        int s = wsum[lane];
        #pragma unroll
        for (int o = 1; o < 32; o <<= 1) {
            int y = __shfl_up_sync(0xffffffffu, s, o);
            if (lane >= o) s += y;
        }
        wsum[lane] = s;
    }
    __syncthreads();
    int off = (wp ? wsum[wp - 1] : 0);
    if (i < NN) g_rowoff[i] = off + x - v;
    if (t == 1023) g_bsum[blockIdx.x] = wsum[31];
}

__global__ void k_scanB(int nb) {
    __shared__ int sh[4];
    int t = threadIdx.x, lane = t & 31, wp = t >> 5;
    int v = (t < nb) ? g_bsum[t] : 0;
    int x = v;
    #pragma unroll
    for (int o = 1; o < 32; o <<= 1) {
        int y = __shfl_up_sync(0xffffffffu, x, o);
        if (lane >= o) x += y;
    }
    if (lane == 31) sh[wp] = x;
    __syncthreads();
    int add = 0;
    for (int w = 0; w < wp; ++w) add += sh[w];
    if (t < 128) g_boff[t] = add + x - v;
}

// scanC + dinv fused
__global__ void k_scanC() {
    int i = blockIdx.x * blockDim.x + threadIdx.x;
    if (i < NN) {
        int r = g_rowoff[i] + g_boff[i >> 10];
        g_rowoff[i] = r;
        g_cursor[i] = r;
        int d = g_deg[i];
        float df = (float)(d > 1 ? d : 1);
        g_dinv[i] = rsqrtf(df);
        g_rdinv[i] = sqrtf(df);
    }
    if (i == 0) g_rowoff[NN] = NE;
}

__global__ void k_scatter(const int* __restrict__ src, const int* __restrict__ dst) {
    int e = blockIdx.x * blockDim.x + threadIdx.x;
    if (e < NE) {
        int p = atomicAdd(&g_cursor[dst[e]], 1);
        g_csr[p] = src[e];
    }
}

// ======================= input conversion =======================
__global__ void k_featsplit(const float* __restrict__ f) {
    size_t i = ((size_t)blockIdx.x * blockDim.x + threadIdx.x) * 4;
    if (i >= (size_t)NN * FH) return;
    int row = (int)(i >> 7);
    float dv = g_dinv[row];
    float4 v = *(const float4*)(f + i);
    uint2 q;
    q.x = f2h2(v.x * dv, v.y * dv);
    q.y = f2h2(v.z * dv, v.w * dv);
    *(uint2*)(&g_F0[0][i]) = q;
}

__global__ void k_prep_w(const float* __restrict__ W0, const float* __restrict__ Wh) {
    int i = blockIdx.x * blockDim.x + threadIdx.x;
    if (i >= 6 * 384 * 128) return;
    int l = i / (384 * 128);
    int r = i % (384 * 128);
    int k = r / 128, n = r % 128;
    const float* W = (l == 0) ? W0 : (Wh + (size_t)(l - 1) * 384 * 128);
    float v = W[(size_t)k * 128 + n];
    __half h = __float2half_rn(v);
    float lo = v - __half2float(h);
    size_t o = (size_t)l * 128 * 384 + (size_t)n * 384 + k;
    g_Wh[o] = h;
    g_Wl[o] = __float2half_rn(lo);
}

// final-layer weights: Wl [384, 40] -> W^T padded [64][384] hi/lo
__global__ void k_prep_wf(const float* __restrict__ Wl) {
    int i = blockIdx.x * blockDim.x + threadIdx.x;
    if (i >= 64 * 384) return;
    int n = i / 384, k = i % 384;
    float v = (n < FO) ? Wl[(size_t)k * FO + n] : 0.f;
    __half h = __float2half_rn(v);
    float lo = v - __half2float(h);
    g_WFh[i] = h;
    g_WFl[i] = __float2half_rn(lo);
}

// ======================= SpMM: warp-per-node CSR gather, fp16 in/out ============
// All planes prescaled by dinv. MODE 1: X1p = -dv^2*sum  MODE 2: X2p = -2dv^2*sum - X0p
template <int MODE>
__global__ void __launch_bounds__(256) k_spmm(
    const __half* __restrict__ Y,
    const __half* __restrict__ X0,
    __half* __restrict__ o) {
    int w = (blockIdx.x * blockDim.x + threadIdx.x) >> 5;
    int lane = threadIdx.x & 31;
    if (w >= NN) return;
    int beg = g_rowoff[w];
    int end = g_rowoff[w + 1];
    const size_t lo4 = (size_t)(lane * 4);
    float a0 = 0.f, a1 = 0.f, a2 = 0.f, a3 = 0.f;
    int i = beg;
    for (; i + 4 <= end; i += 4) {
        int s0 = g_csr[i], s1 = g_csr[i + 1], s2 = g_csr[i + 2], s3 = g_csr[i + 3];
        uint2 u0 = *(const uint2*)(Y + (size_t)s0 * FH + lo4);
        uint2 u1 = *(const uint2*)(Y + (size_t)s1 * FH + lo4);
        uint2 u2 = *(const uint2*)(Y + (size_t)s2 * FH + lo4);
        uint2 u3 = *(const uint2*)(Y + (size_t)s3 * FH + lo4);
        float2 f;
        f = h2f2(u0.x); a0 += f.x; a1 += f.y;
        f = h2f2(u0.y); a2 += f.x; a3 += f.y;
        f = h2f2(u1.x); a0 += f.x; a1 += f.y;
        f = h2f2(u1.y); a2 += f.x; a3 += f.y;
        f = h2f2(u2.x); a0 += f.x; a1 += f.y;
        f = h2f2(u2.y); a2 += f.x; a3 += f.y;
        f = h2f2(u3.x); a0 += f.x; a1 += f.y;
        f = h2f2(u3.y); a2 += f.x; a3 += f.y;
    }
    for (; i < end; ++i) {
        int s0 = g_csr[i];
        uint2 u0 = *(const uint2*)(Y + (size_t)s0 * FH + lo4);
        float2 f;
        f = h2f2(u0.x); a0 += f.x; a1 += f.y;
        f = h2f2(u0.y); a2 += f.x; a3 += f.y;
    }
    float dv = g_dinv[w];
    float dv2 = dv * dv;
    float p0, p1, p2, p3;
    if (MODE == 1) {
        float m = -dv2;
        p0 = m * a0; p1 = m * a1; p2 = m * a2; p3 = m * a3;
    } else {
        uint2 xq = *(const uint2*)(X0 + (size_t)w * FH + lo4);
        float2 x0 = h2f2(xq.x), x1 = h2f2(xq.y);
        float m = -2.f * dv2;
        p0 = fmaf(m, a0, -x0.x);
        p1 = fmaf(m, a1, -x0.y);
        p2 = fmaf(m, a2, -x1.x);
        p3 = fmaf(m, a3, -x1.y);
    }
    uint2 q;
    q.x = f2h2(p0, p1);
    q.y = f2h2(p2, p3);
    *(uint2*)(o + (size_t)w * FH + lo4) = q;
}

// ======================= pipelined mma.sync GEMM, fp16 A, f16-pair weights ======
// (exact R12 champion) C = relu( rdinv[m]*(A@(Wh+Wl)) + b ); store (C*dinv) fp16.
#define GS_A   0
#define GS_BHI 16384
#define GS_BLO 32768
#define GS_ST  49152
#define GM_SMEM_SZ (2 * GS_ST)

__global__ void __launch_bounds__(512, 2) k_gemm_mma(
    const __half* __restrict__ x0,
    const float* __restrict__ bias,
    const __half* __restrict__ wh, const __half* __restrict__ wl,
    __half* __restrict__ outp) {
    extern __shared__ char smem_raw[];
    __shared__ float s_bias[128];
    uint32_t sb0 = smem_u32(smem_raw);
    uint32_t sb = (sb0 + 1023u) & ~1023u;

    const int tid = threadIdx.x, lane = tid & 31, wid = tid >> 5;
    const int wm = wid >> 2, wn = wid & 3;
    const int rowBase = blockIdx.x * 128;
    if (tid < 128) s_bias[tid] = bias[tid];
    __syncthreads();

    const __half* Ap[3] = {x0, g_F1, g_F2};

    float acc[2][4][4];
    #pragma unroll
    for (int a = 0; a < 2; ++a)
        #pragma unroll
        for (int b = 0; b < 4; ++b)
            #pragma unroll
            for (int c = 0; c < 4; ++c) acc[a][b][c] = 0.f;

    const int lrow = lane & 7, seg = lane >> 3;

    auto load_chunk = [&](uint32_t st, int kc) {
        const int coff = (kc & 1) * 64;
        const __half* __restrict__ ap = Ap[kc >> 1];
        #pragma unroll
        for (int t = 0; t < 2; ++t) {
            int idx = tid + t * 512;
            int r = idx >> 3, j = idx & 7;
            int row = rowBase + r;
            bool ok = row < NN;
            int rowc = ok ? row : (NN - 1);
            uint32_t sw = SWZ((uint32_t)(r * 128 + j * 16));
            cpa16(st + GS_A + sw, ap + (size_t)rowc * FH + coff + j * 8, ok);
        }
        #pragma unroll
        for (int t = 0; t < 2; ++t) {
            int idx = tid + t * 512;
            int n = idx >> 3, j = idx & 7;
            uint32_t sw = SWZ((uint32_t)(n * 128 + j * 16));
            cpa16(st + GS_BHI + sw, wh + (size_t)n * 384 + kc * 64 + j * 8, true);
            cpa16(st + GS_BLO + sw, wl + (size_t)n * 384 + kc * 64 + j * 8, true);
        }
    };

    load_chunk(sb, 0);
    CP_COMMIT();

    #pragma unroll 1
    for (int kc = 0; kc < 6; ++kc) {
        if (kc < 5) {
            load_chunk(sb + (((kc + 1) & 1) ? GS_ST : 0), kc + 1);
            CP_COMMIT();
            CP_WAIT(1);
        } else {
            CP_WAIT(0);
        }
        __syncthreads();

        const uint32_t st = sb + ((kc & 1) ? GS_ST : 0);
        #pragma unroll
        for (int kt = 0; kt < 4; ++kt) {
            uint32_t Af[2][4], Bhf[2][4], Blf[2][4];
            #pragma unroll
            for (int mt = 0; mt < 2; ++mt) {
                int m = wm * 32 + mt * 16 + (seg & 1) * 8 + lrow;
                int kb = kt * 32 + (seg >> 1) * 16;
                uint32_t sw = SWZ((uint32_t)(m * 128 + kb));
                ldmx4(Af[mt], st + GS_A + sw);
            }
            #pragma unroll
            for (int ntp = 0; ntp < 2; ++ntp) {
                int n = wn * 32 + ntp * 16 + (seg >> 1) * 8 + lrow;
                int kb = kt * 32 + (seg & 1) * 16;
                uint32_t sw = SWZ((uint32_t)(n * 128 + kb));
                ldmx4(Bhf[ntp], st + GS_BHI + sw);
                ldmx4(Blf[ntp], st + GS_BLO + sw);
            }
            #pragma unroll
            for (int mt = 0; mt < 2; ++mt)
                #pragma unroll
                for (int ntp = 0; ntp < 2; ++ntp)
                    #pragma unroll
                    for (int sub = 0; sub < 2; ++sub) {
                        int nj = ntp * 2 + sub;
                        mma_f16(acc[mt][nj], Af[mt], &Bhf[ntp][sub * 2]);
                        mma_f16(acc[mt][nj], Af[mt], &Blf[ntp][sub * 2]);
                    }
        }
        __syncthreads();
    }

    #pragma unroll
    for (int mt = 0; mt < 2; ++mt) {
        #pragma unroll
        for (int rp = 0; rp < 2; ++rp) {
            int row = rowBase + wm * 32 + mt * 16 + (lane >> 2) + rp * 8;
            if (row < NN) {
                float dv = g_dinv[row], rd = g_rdinv[row];
                #pragma unroll
                for (int nj = 0; nj < 4; ++nj) {
                    int col = wn * 32 + nj * 8 + (lane & 3) * 2;
                    float bz0 = s_bias[col], bz1 = s_bias[col + 1];
                    float p0 = fmaxf(fmaf(acc[mt][nj][rp * 2 + 0], rd, bz0), 0.f) * dv;
                    float p1 = fmaxf(fmaf(acc[mt][nj][rp * 2 + 1], rd, bz1), 0.f) * dv;
                    *(uint32_t*)(outp + (size_t)row * FH + col) = f2h2(p0, p1);
                }
            }
        }
    }
}

// ======================= final layer: mma GEMM, N padded to 64 ==================
// out[row, col<40] = relu( rdinv[row]*(A@(WFh+WFl)) + bl ), fp32 direct store.
// 256 threads, 4x2 warp grid (32x32 warp tiles). Stage: A 16K | Bh 8K | Bl 8K = 32K.
#define GF_A   0
#define GF_BHI 16384
#define GF_BLO 24576
#define GF_ST  32768
#define GF_SMEM_SZ (2 * GF_ST)

__global__ void __launch_bounds__(256, 3) k_gemm_final(
    const __half* __restrict__ x0,
    const float* __restrict__ bias,
    float* __restrict__ out) {
    extern __shared__ char smem_raw[];
    __shared__ float s_bias[64];
    uint32_t sb0 = smem_u32(smem_raw);
    uint32_t sb = (sb0 + 1023u) & ~1023u;

    const int tid = threadIdx.x, lane = tid & 31, wid = tid >> 5;
    const int wm = wid >> 1, wn = wid & 1;        // 4x2 warp grid
    const int rowBase = blockIdx.x * 128;
    if (tid < 64) s_bias[tid] = (tid < FO) ? bias[tid] : 0.f;
    __syncthreads();

    const __half* Ap[3] = {x0, g_F1, g_F2};

    float acc[2][4][4];
    #pragma unroll
    for (int a = 0; a < 2; ++a)
        #pragma unroll
        for (int b = 0; b < 4; ++b)
            #pragma unroll
            for (int c = 0; c < 4; ++c) acc[a][b][c] = 0.f;

    const int lrow = lane & 7, seg = lane >> 3;

    auto load_chunk = [&](uint32_t st, int kc) {
        const int coff = (kc & 1) * 64;
        const __half* __restrict__ ap = Ap[kc >> 1];
        #pragma unroll
        for (int t = 0; t < 4; ++t) {
            int idx = tid + t * 256;
            int r = idx >> 3, j = idx & 7;
            int row = rowBase + r;
            bool ok = row < NN;
            int rowc = ok ? row : (NN - 1);
            uint32_t sw = SWZ((uint32_t)(r * 128 + j * 16));
            cpa16(st + GF_A + sw, ap + (size_t)rowc * FH + coff + j * 8, ok);
        }
        #pragma unroll
        for (int t = 0; t < 2; ++t) {
            int idx = tid + t * 256;
            int n = idx >> 3, j = idx & 7;
            uint32_t sw = SWZ((uint32_t)(n * 128 + j * 16));
            cpa16(st + GF_BHI + sw, g_WFh + (size_t)n * 384 + kc * 64 + j * 8, true);
            cpa16(st + GF_BLO + sw, g_WFl + (size_t)n * 384 + kc * 64 + j * 8, true);
        }
    };

    load_chunk(sb, 0);
    CP_COMMIT();

    #pragma unroll 1
    for (int kc = 0; kc < 6; ++kc) {
        if (kc < 5) {
            load_chunk(sb + (((kc + 1) & 1) ? GF_ST : 0), kc + 1);
            CP_COMMIT();
            CP_WAIT(1);
        } else {
            CP_WAIT(0);
        }
        __syncthreads();

        const uint32_t st = sb + ((kc & 1) ? GF_ST : 0);
        #pragma unroll
        for (int kt = 0; kt < 4; ++kt) {
            uint32_t Af[2][4], Bhf[2][4], Blf[2][4];
            #pragma unroll
            for (int mt = 0; mt < 2; ++mt) {
                int m = wm * 32 + mt * 16 + (seg & 1) * 8 + lrow;
                int kb = kt * 32 + (seg >> 1) * 16;
                uint32_t sw = SWZ((uint32_t)(m * 128 + kb));
                ldmx4(Af[mt], st + GF_A + sw);
            }
            #pragma unroll
            for (int ntp = 0; ntp < 2; ++ntp) {
                int n = wn * 32 + ntp * 16 + (seg >> 1) * 8 + lrow;
                int kb = kt * 32 + (seg & 1) * 16;
                uint32_t sw = SWZ((uint32_t)(n * 128 + kb));
                ldmx4(Bhf[ntp], st + GF_BHI + sw);
                ldmx4(Blf[ntp], st + GF_BLO + sw);
            }
            #pragma unroll
            for (int mt = 0; mt < 2; ++mt)
                #pragma unroll
                for (int ntp = 0; ntp < 2; ++ntp)
                    #pragma unroll
                    for (int sub = 0; sub < 2; ++sub) {
                        int nj = ntp * 2 + sub;
                        mma_f16(acc[mt][nj], Af[mt], &Bhf[ntp][sub * 2]);
                        mma_f16(acc[mt][nj], Af[mt], &Blf[ntp][sub * 2]);
                    }
        }
        __syncthreads();
    }

    // epilogue: fp32 out, cols < 40 only
    #pragma unroll
    for (int mt = 0; mt < 2; ++mt) {
        #pragma unroll
        for (int rp = 0; rp < 2; ++rp) {
            int row = rowBase + wm * 32 + mt * 16 + (lane >> 2) + rp * 8;
            if (row < NN) {
                float rd = g_rdinv[row];
                #pragma unroll
                for (int nj = 0; nj < 4; ++nj) {
                    int col = wn * 32 + nj * 8 + (lane & 3) * 2;
                    if (col < FO) {
                        float bz0 = s_bias[col], bz1 = s_bias[col + 1];
                        float p0 = fmaxf(fmaf(acc[mt][nj][rp * 2 + 0], rd, bz0), 0.f);
                        float p1 = fmaxf(fmaf(acc[mt][nj][rp * 2 + 1], rd, bz1), 0.f);
                        *(float2*)(out + (size_t)row * FO + col) = make_float2(p0, p1);
                    }
                }
            }
        }
    }
}

// ======================= host launcher =======================
extern "C" void kernel_launch(void* const* d_in, const int* in_sizes, int n_in,
                              void* d_out, int out_size) {
    const float* feat = (const float*)d_in[0];
    const int*   src  = (const int*)d_in[1];
    const int*   dst  = (const int*)d_in[2];
    const float* W0   = (const float*)d_in[3];
    const float* b0   = (const float*)d_in[4];
    const float* Wh_  = (const float*)d_in[5];
    const float* bh   = (const float*)d_in[6];
    const float* Wl_  = (const float*)d_in[7];
    const float* bl   = (const float*)d_in[8];
    float* out = (float*)d_out;

    __half *F0, *F1, *F2, *Wh, *Wl;
    int* degp;
    cudaGetSymbolAddress((void**)&F0, g_F0);
    cudaGetSymbolAddress((void**)&F1, g_F1);
    cudaGetSymbolAddress((void**)&F2, g_F2);
    cudaGetSymbolAddress((void**)&Wh, g_Wh);
    cudaGetSymbolAddress((void**)&Wl, g_Wl);
    cudaGetSymbolAddress((void**)&degp, g_deg);

    cudaFuncSetAttribute(k_gemm_mma, cudaFuncAttributeMaxDynamicSharedMemorySize,
                         GM_SMEM_SZ + 1024);
    cudaFuncSetAttribute(k_gemm_final, cudaFuncAttributeMaxDynamicSharedMemorySize,
                         GF_SMEM_SZ + 1024);

    const int TPB = 256;
    const int nodeBlocks = (NN + TPB - 1) / TPB;
    const int edgeBlocks = (NE + TPB - 1) / TPB;
    const int scanBlocks = (NN + 1023) / 1024;   // 98

    // preprocessing
    cudaMemsetAsync(degp, 0, NN * sizeof(int));
    k_hist<<<edgeBlocks, TPB>>>(dst);
    k_scanA<<<scanBlocks, 1024>>>();
    k_scanB<<<1, 128>>>(scanBlocks);
    k_scanC<<<nodeBlocks, TPB>>>();   // + dinv/rdinv
    k_scatter<<<edgeBlocks, TPB>>>(src, dst);

    // input conversion
    k_featsplit<<<(NN * FH / 4 + TPB - 1) / TPB, TPB>>>(feat);
    k_prep_w<<<(6 * 384 * 128 + TPB - 1) / TPB, TPB>>>(W0, Wh_);
    k_prep_wf<<<(64 * 384 + TPB - 1) / TPB, TPB>>>(Wl_);

    const size_t SL = (size_t)NN * FH;
    const int spmmBlocks = (NN * 32 + TPB - 1) / TPB;
    const int tileBlocks = (NN + 127) / 128;

    int cur = 0;
    for (int l = 0; l < 7; ++l) {
        const __half* F0c = F0 + (size_t)cur * SL;
        k_spmm<1><<<spmmBlocks, TPB>>>(F0c, nullptr, F1);
        k_spmm<2><<<spmmBlocks, TPB>>>(F1, F0c, F2);
        if (l < 6) {
            const float* bias = (l == 0) ? b0 : (bh + (size_t)(l - 1) * 128);
            int nxt = 1 - cur;
            k_gemm_mma<<<tileBlocks, 512, GM_SMEM_SZ + 1024>>>(
                F0c, bias,
                Wh + (size_t)l * 128 * 384, Wl + (size_t)l * 128 * 384,
                F0 + (size_t)nxt * SL);
            cur = nxt;
        } else {
            k_gemm_final<<<tileBlocks, 256, GF_SMEM_SZ + 1024>>>(F0c, bl, out);
        }
    }
}